// round 4
// baseline (speedup 1.0000x reference)
#include <cuda_runtime.h>
#include <cstdint>

// Problem constants
#define Bc 4
#define Tc 2048
#define Cc 1024
#define Hc 16
#define Dc 64
#define BHTD ((size_t)Bc * Hc * Tc * Dc)   // 8388608

// Scratch (static device globals — no allocation allowed)
__device__ float g_qkv[3 * Bc * Hc * Tc * Dc];        // [s][B][H][T][D]
__device__ float g_att[(size_t)Bc * Tc * Cc];          // [B,T,C]

__device__ __forceinline__ float neg_inf() { return __int_as_float(0xff800000); }

// ---------------------------------------------------------------------------
// SIMT fp32 GEMM: C[M,N] = A[M,K] @ B[K,N] + bias
// 128x128 tile, BK=16, 256 threads, 8x8 microtile.
// MODE 0: plain write to Cout.
// MODE 1: scatter into g_qkv as [s][B][H][T][D]  (N must be 3*Cc)
// ---------------------------------------------------------------------------
template <int MODE>
__global__ __launch_bounds__(256)
void sgemm_kernel(const float* __restrict__ A, const float* __restrict__ Bm,
                  const float* __restrict__ bias, float* __restrict__ Cout,
                  int M, int N, int K)
{
    __shared__ float As[16][128];
    __shared__ float Bs[16][128];

    const int tid = threadIdx.x;
    const int m0 = blockIdx.y * 128;
    const int n0 = blockIdx.x * 128;
    const int tx = tid & 15;        // column group
    const int ty = tid >> 4;        // row group

    // A loader: each thread loads 8 consecutive k's of one row
    const int arow = tid >> 1;              // 0..127
    const int acol = (tid & 1) * 8;         // 0 or 8
    // B loader: each thread loads 8 consecutive n's of one k-row
    const int brow = tid >> 4;              // 0..15
    const int bcol = (tid & 15) * 8;        // 0..120

    const float* Aptr = A + (size_t)(m0 + arow) * K + acol;
    const float* Bptr = Bm + (size_t)brow * N + n0 + bcol;

    float acc[8][8];
#pragma unroll
    for (int i = 0; i < 8; i++)
#pragma unroll
        for (int j = 0; j < 8; j++) acc[i][j] = 0.0f;

    for (int k0 = 0; k0 < K; k0 += 16) {
        float4 a0 = *(const float4*)(Aptr + k0);
        float4 a1 = *(const float4*)(Aptr + k0 + 4);
        float4 b0 = *(const float4*)(Bptr + (size_t)k0 * N);
        float4 b1 = *(const float4*)(Bptr + (size_t)k0 * N + 4);

        __syncthreads();   // previous iteration's smem reads complete
        As[acol + 0][arow] = a0.x;
        As[acol + 1][arow] = a0.y;
        As[acol + 2][arow] = a0.z;
        As[acol + 3][arow] = a0.w;
        As[acol + 4][arow] = a1.x;
        As[acol + 5][arow] = a1.y;
        As[acol + 6][arow] = a1.z;
        As[acol + 7][arow] = a1.w;
        *(float4*)&Bs[brow][bcol]     = b0;
        *(float4*)&Bs[brow][bcol + 4] = b1;
        __syncthreads();

#pragma unroll
        for (int kk = 0; kk < 16; kk++) {
            float4 av0 = *(const float4*)&As[kk][ty * 8];
            float4 av1 = *(const float4*)&As[kk][ty * 8 + 4];
            float4 bv0 = *(const float4*)&Bs[kk][tx * 8];
            float4 bv1 = *(const float4*)&Bs[kk][tx * 8 + 4];
            float a[8] = {av0.x, av0.y, av0.z, av0.w, av1.x, av1.y, av1.z, av1.w};
            float b[8] = {bv0.x, bv0.y, bv0.z, bv0.w, bv1.x, bv1.y, bv1.z, bv1.w};
#pragma unroll
            for (int i = 0; i < 8; i++)
#pragma unroll
                for (int j = 0; j < 8; j++)
                    acc[i][j] = fmaf(a[i], b[j], acc[i][j]);
        }
    }

    if (MODE == 0) {
#pragma unroll
        for (int i = 0; i < 8; i++) {
            const size_t row = (size_t)(m0 + ty * 8 + i);
#pragma unroll
            for (int j = 0; j < 8; j++) {
                const int col = n0 + tx * 8 + j;
                Cout[row * N + col] = acc[i][j] + bias[col];
            }
        }
    } else {
        // scatter into g_qkv [s][B][H][T][D]; r -> (b,t), c -> (s,h,d)
#pragma unroll
        for (int i = 0; i < 8; i++) {
            const int r = m0 + ty * 8 + i;
            const int b = r >> 11;              // /Tc
            const int t = r & (Tc - 1);
#pragma unroll
            for (int j = 0; j < 8; j++) {
                const int c = n0 + tx * 8 + j;
                const int s = c >> 10;          // /Cc
                const int rem = c & (Cc - 1);
                const int h = rem >> 6;         // /Dc
                const int d = rem & (Dc - 1);
                const size_t dst =
                    ((((size_t)(s * Bc + b) * Hc + h) * Tc + t) << 6) + d;
                g_qkv[dst] = acc[i][j] + bias[c];
            }
        }
    }
}

// ---------------------------------------------------------------------------
// Flash attention, fp32. 1 thread = 1 query. Block = 128 queries.
// K/V tiles 32x64 in smem; all smem reads uniform across warp (broadcast).
// Writes output directly in [B,T,C] layout.
// ---------------------------------------------------------------------------
__global__ __launch_bounds__(128)
void attn_kernel(const float* __restrict__ Q, const float* __restrict__ K,
                 const float* __restrict__ V, float* __restrict__ O)
{
    __shared__ float Ks[32][64];
    __shared__ float Vs[32][64];

    const int tid = threadIdx.x;
    const int bh = blockIdx.y;            // b*H + h
    const int b = bh >> 4;
    const int h = bh & 15;
    const int qi = blockIdx.x * 128 + tid;

    // fold scale (1/sqrt(D)) and log2(e) into q  -> softmax in exp2 domain
    const float SCALE = 0.125f * 1.44269504088896340736f;

    const float* qptr = Q + ((size_t)bh * Tc + qi) * Dc;
    float q[64];
#pragma unroll
    for (int d = 0; d < 64; d += 4) {
        float4 v4 = *(const float4*)(qptr + d);
        q[d + 0] = v4.x * SCALE;
        q[d + 1] = v4.y * SCALE;
        q[d + 2] = v4.z * SCALE;
        q[d + 3] = v4.w * SCALE;
    }

    float acc[64];
#pragma unroll
    for (int d = 0; d < 64; d++) acc[d] = 0.0f;
    float m = neg_inf();
    float l = 0.0f;

    const int limit = blockIdx.x * 128 + 128;      // causal: keys [0, limit)
    const float* kbase = K + (size_t)bh * Tc * Dc;
    const float* vbase = V + (size_t)bh * Tc * Dc;

    for (int t0 = 0; t0 < limit; t0 += 32) {
        __syncthreads();
#pragma unroll
        for (int c2 = 0; c2 < 4; c2++) {
            const int lin = c2 * 512 + tid * 4;
            const int row = lin >> 6;
            const int col = lin & 63;
            *(float4*)&Ks[row][col] =
                *(const float4*)(kbase + (size_t)(t0 + row) * Dc + col);
            *(float4*)&Vs[row][col] =
                *(const float4*)(vbase + (size_t)(t0 + row) * Dc + col);
        }
        __syncthreads();

        float s[32];
        float mt = m;
#pragma unroll 4
        for (int j = 0; j < 32; j++) {
            const float4* kr = (const float4*)Ks[j];
            float s0 = 0.f, s1 = 0.f, s2 = 0.f, s3 = 0.f;
#pragma unroll
            for (int d4 = 0; d4 < 16; d4++) {
                float4 kv = kr[d4];
                s0 = fmaf(q[d4 * 4 + 0], kv.x, s0);
                s1 = fmaf(q[d4 * 4 + 1], kv.y, s1);
                s2 = fmaf(q[d4 * 4 + 2], kv.z, s2);
                s3 = fmaf(q[d4 * 4 + 3], kv.w, s3);
            }
            float sum = (s0 + s1) + (s2 + s3);
            s[j] = (t0 + j <= qi) ? sum : neg_inf();
            mt = fmaxf(mt, s[j]);
        }

        const float alpha = exp2f(m - mt);   // m=-inf only before any valid key
        m = mt;
        l *= alpha;
#pragma unroll
        for (int d = 0; d < 64; d++) acc[d] *= alpha;

#pragma unroll 4
        for (int j = 0; j < 32; j++) {
            const float p = exp2f(s[j] - mt);   // masked -> exp2(-inf) = 0
            l += p;
            const float4* vr = (const float4*)Vs[j];
#pragma unroll
            for (int d4 = 0; d4 < 16; d4++) {
                float4 vv = vr[d4];
                acc[d4 * 4 + 0] = fmaf(p, vv.x, acc[d4 * 4 + 0]);
                acc[d4 * 4 + 1] = fmaf(p, vv.y, acc[d4 * 4 + 1]);
                acc[d4 * 4 + 2] = fmaf(p, vv.z, acc[d4 * 4 + 2]);
                acc[d4 * 4 + 3] = fmaf(p, vv.w, acc[d4 * 4 + 3]);
            }
        }
    }

    const float inv = 1.0f / l;   // diagonal key always present -> l > 0
    float* optr = O + ((size_t)b * Tc + qi) * Cc + h * Dc;
#pragma unroll
    for (int d = 0; d < 64; d += 4) {
        float4 o4;
        o4.x = acc[d + 0] * inv;
        o4.y = acc[d + 1] * inv;
        o4.z = acc[d + 2] * inv;
        o4.w = acc[d + 3] * inv;
        *(float4*)(optr + d) = o4;
    }
}

// ---------------------------------------------------------------------------
// Host launcher
// ---------------------------------------------------------------------------
extern "C" void kernel_launch(void* const* d_in, const int* in_sizes, int n_in,
                              void* d_out, int out_size)
{
    const float* x    = (const float*)d_in[0];
    // d_in[1] = mask (causal, known statically — unused)
    const float* Wqkv = (const float*)d_in[2];
    const float* bqkv = (const float*)d_in[3];
    const float* Wout = (const float*)d_in[4];
    const float* bout = (const float*)d_in[5];
    float* out = (float*)d_out;

    float* qkv = nullptr;
    float* att = nullptr;
    cudaGetSymbolAddress((void**)&qkv, g_qkv);
    cudaGetSymbolAddress((void**)&att, g_att);

    const int M = Bc * Tc;       // 8192

    // 1) QKV GEMM + bias, scattered into [s][B][H][T][D]
    {
        dim3 grid((3 * Cc) / 128, M / 128);   // (24, 64)
        sgemm_kernel<1><<<grid, 256>>>(x, Wqkv, bqkv, nullptr, M, 3 * Cc, Cc);
    }

    // 2) causal flash attention -> g_att in [B,T,C]
    {
        const float* Qp = qkv;
        const float* Kp = qkv + BHTD;
        const float* Vp = qkv + 2 * BHTD;
        dim3 grid(Tc / 128, Bc * Hc);         // (16, 64)
        attn_kernel<<<grid, 128>>>(Qp, Kp, Vp, att);
    }

    // 3) output projection + bias -> d_out
    {
        dim3 grid(Cc / 128, M / 128);         // (8, 64)
        sgemm_kernel<0><<<grid, 256>>>(att, Wout, bout, out, M, Cc, Cc);
    }
}

// round 7
// speedup vs baseline: 1.5834x; 1.5834x over previous
#include <cuda_runtime.h>
#include <cstdint>

// Problem constants
#define Bc 4
#define Tc 2048
#define Cc 1024
#define Hc 16
#define Dc 64
#define BHTD ((size_t)Bc * Hc * Tc * Dc)   // 8388608

// Scratch (static device globals — no allocation allowed)
__device__ float g_qkv[3 * Bc * Hc * Tc * Dc];        // [s][B][H][T][D]
__device__ float g_att[(size_t)Bc * Tc * Cc];          // [B,T,C] (tf32-rounded)
__device__ float g_xr[(size_t)Bc * Tc * Cc];           // x, tf32-rounded
__device__ float g_wqkvT[3 * Cc * Cc];                 // Wqkv^T [3072,1024], tf32-rounded
__device__ float g_woutT[(size_t)Cc * Cc];             // Wout^T [1024,1024], tf32-rounded

__device__ __forceinline__ float neg_inf() { return __int_as_float(0xff800000); }

__device__ __forceinline__ float tf32r(float x) {
    float y;
    asm("cvt.rna.tf32.f32 %0, %1;" : "=f"(y) : "f"(x));
    return y;
}

__device__ __forceinline__ uint32_t smem_u32(const void* p) {
    uint32_t a;
    asm("{ .reg .u64 t; cvta.to.shared.u64 t, %1; cvt.u32.u64 %0, t; }"
        : "=r"(a) : "l"(p));
    return a;
}

__device__ __forceinline__ void cp_async16(uint32_t smem_dst, const void* gsrc) {
    asm volatile("cp.async.cg.shared.global [%0], [%1], 16;"
                 :: "r"(smem_dst), "l"(gsrc) : "memory");
}
__device__ __forceinline__ void cp_async_commit() {
    asm volatile("cp.async.commit_group;" ::: "memory");
}
__device__ __forceinline__ void cp_async_wait0() {
    asm volatile("cp.async.wait_group 0;" ::: "memory");
}

// mma.sync m16n8k8 tf32 (A row-major, B col-major, fp32 accum)
__device__ __forceinline__ void mma_tf32(float* d, const uint32_t* a, const uint32_t* b) {
    asm volatile(
        "mma.sync.aligned.m16n8k8.row.col.f32.tf32.tf32.f32 "
        "{%0,%1,%2,%3}, {%4,%5,%6,%7}, {%8,%9}, {%0,%1,%2,%3};"
        : "+f"(d[0]), "+f"(d[1]), "+f"(d[2]), "+f"(d[3])
        : "r"(a[0]), "r"(a[1]), "r"(a[2]), "r"(a[3]), "r"(b[0]), "r"(b[1]));
}

// ---------------------------------------------------------------------------
// Elementwise tf32 rounding: out[i] = rna_tf32(in[i]); n % 4 == 0
// ---------------------------------------------------------------------------
__global__ __launch_bounds__(256)
void round_kernel(const float* __restrict__ in, float* __restrict__ out, int n)
{
    const int i = (blockIdx.x * 256 + threadIdx.x) * 4;
    if (i < n) {
        float4 v = *(const float4*)(in + i);
        v.x = tf32r(v.x); v.y = tf32r(v.y); v.z = tf32r(v.z); v.w = tf32r(v.w);
        *(float4*)(out + i) = v;
    }
}

// ---------------------------------------------------------------------------
// Transpose + tf32 round: out[c][r] = rna_tf32(in[r][c])  (R rows, C cols)
// ---------------------------------------------------------------------------
__global__ __launch_bounds__(256)
void transpose_kernel(const float* __restrict__ in, float* __restrict__ out,
                      int R, int C)
{
    __shared__ float tile[32][33];
    const int c0 = blockIdx.x * 32;
    const int r0 = blockIdx.y * 32;
    const int x = threadIdx.x & 31;
    const int y = threadIdx.x >> 5;          // 0..7
#pragma unroll
    for (int i = 0; i < 32; i += 8)
        tile[y + i][x] = in[(size_t)(r0 + y + i) * C + c0 + x];
    __syncthreads();
#pragma unroll
    for (int i = 0; i < 32; i += 8)
        out[(size_t)(c0 + y + i) * R + r0 + x] = tf32r(tile[x][y + i]);
}

// ---------------------------------------------------------------------------
// tf32 mma.sync GEMM:  C[M,N] = A[M,K] @ Bt[N,K]^T + bias
// CTA 128x128, 256 threads = 8 warps (2m x 4n), warp tile 64x32, BK=16.
// Double-buffered cp.async. Inputs must already be tf32-rounded.
// MODE 0: plain write.  MODE 1: scatter into g_qkv [s][B][H][T][D].
// ---------------------------------------------------------------------------
#define PAD 20           // smem row stride in floats (16 data + 4 pad)

template <int MODE>
__global__ __launch_bounds__(256)
void gemm_mma(const float* __restrict__ A, const float* __restrict__ Bt,
              const float* __restrict__ bias, float* __restrict__ Cout,
              int M, int N, int K)
{
    __shared__ float As[2][128 * PAD];
    __shared__ float Bs[2][128 * PAD];

    const int tid = threadIdx.x;
    const int wid = tid >> 5;
    const int lid = tid & 31;
    const int g   = lid >> 2;       // group id 0..7
    const int tg  = lid & 3;        // thread-in-group 0..3
    const int wm  = (wid >> 2) * 64;     // warp m offset in CTA tile
    const int wn  = (wid & 3) * 32;      // warp n offset

    const int m0 = blockIdx.y * 128;
    const int n0 = blockIdx.x * 128;
    const int KT = K >> 4;               // number of BK=16 stages

    // loader mapping: 512 16B chunks per operand, 2 per thread
    const int lrow0 = tid >> 2;          // chunk tid  : row 0..63
    const int lrow1 = (tid + 256) >> 2;  //          : row 64..127
    const int lc16  = tid & 3;           // 16B chunk within row

    float acc[4][4][4];
#pragma unroll
    for (int i = 0; i < 4; i++)
#pragma unroll
        for (int j = 0; j < 4; j++)
#pragma unroll
            for (int r = 0; r < 4; r++) acc[i][j][r] = 0.0f;

    auto load_stage = [&](int kt, int buf) {
        const float* ga = A  + (size_t)m0 * K + kt * 16;
        const float* gb = Bt + (size_t)n0 * K + kt * 16;
        const uint32_t sa = smem_u32(&As[buf][0]);
        const uint32_t sb = smem_u32(&Bs[buf][0]);
        cp_async16(sa + (lrow0 * PAD + lc16 * 4) * 4, ga + (size_t)lrow0 * K + lc16 * 4);
        cp_async16(sa + (lrow1 * PAD + lc16 * 4) * 4, ga + (size_t)lrow1 * K + lc16 * 4);
        cp_async16(sb + (lrow0 * PAD + lc16 * 4) * 4, gb + (size_t)lrow0 * K + lc16 * 4);
        cp_async16(sb + (lrow1 * PAD + lc16 * 4) * 4, gb + (size_t)lrow1 * K + lc16 * 4);
    };

    load_stage(0, 0);
    cp_async_commit();

    for (int kt = 0; kt < KT; kt++) {
        const int buf = kt & 1;
        cp_async_wait0();
        __syncthreads();
        if (kt + 1 < KT) {
            load_stage(kt + 1, (kt + 1) & 1);
            cp_async_commit();
        }

#pragma unroll
        for (int ks = 0; ks < 2; ks++) {
            uint32_t af[4][4], bf[4][2];
#pragma unroll
            for (int i = 0; i < 4; i++) {
                const uint32_t* p = (const uint32_t*)
                    &As[buf][(wm + i * 16 + g) * PAD + ks * 8 + tg];
                af[i][0] = p[0];
                af[i][1] = p[8 * PAD];
                af[i][2] = p[4];
                af[i][3] = p[8 * PAD + 4];
            }
#pragma unroll
            for (int j = 0; j < 4; j++) {
                const uint32_t* p = (const uint32_t*)
                    &Bs[buf][(wn + j * 8 + g) * PAD + ks * 8 + tg];
                bf[j][0] = p[0];
                bf[j][1] = p[4];
            }
#pragma unroll
            for (int i = 0; i < 4; i++)
#pragma unroll
                for (int j = 0; j < 4; j++)
                    mma_tf32(acc[i][j], af[i], bf[j]);
        }
        __syncthreads();
    }

    // epilogue: c0,c1 -> (row g, cols 2tg,2tg+1); c2,c3 -> row g+8
#pragma unroll
    for (int i = 0; i < 4; i++) {
        const int r0 = m0 + wm + i * 16 + g;
        const int r1 = r0 + 8;
#pragma unroll
        for (int j = 0; j < 4; j++) {
            const int c = n0 + wn + j * 8 + 2 * tg;
            const float2 bv = *(const float2*)(bias + c);
            float2 v0, v1;
            v0.x = acc[i][j][0] + bv.x;  v0.y = acc[i][j][1] + bv.y;
            v1.x = acc[i][j][2] + bv.x;  v1.y = acc[i][j][3] + bv.y;
            if (MODE == 0) {
                *(float2*)(Cout + (size_t)r0 * N + c) = v0;
                *(float2*)(Cout + (size_t)r1 * N + c) = v1;
            } else {
                const int sidx = c >> 10;
                const int rem  = c & (Cc - 1);
                const int h    = rem >> 6;
                const int dd   = rem & (Dc - 1);
                const int b0i = r0 >> 11, t0i = r0 & (Tc - 1);
                const int b1i = r1 >> 11, t1i = r1 & (Tc - 1);
                const size_t base = (size_t)(sidx * Bc) * Hc;
                const size_t d0 = (((base + (size_t)b0i * Hc + h) * Tc + t0i) << 6) + dd;
                const size_t d1 = (((base + (size_t)b1i * Hc + h) * Tc + t1i) << 6) + dd;
                *(float2*)&g_qkv[d0] = v0;
                *(float2*)&g_qkv[d1] = v1;
            }
        }
    }
}

// ---------------------------------------------------------------------------
// Flash attention, fp32. 1 thread = 1 query. Block = 128 queries.
// Output is tf32-rounded (it feeds the tf32 projection GEMM).
// ---------------------------------------------------------------------------
__global__ __launch_bounds__(128)
void attn_kernel(const float* __restrict__ Q, const float* __restrict__ K,
                 const float* __restrict__ V, float* __restrict__ O)
{
    __shared__ float Ks[32][64];
    __shared__ float Vs[32][64];

    const int tid = threadIdx.x;
    const int bh = blockIdx.y;
    const int b = bh >> 4;
    const int h = bh & 15;
    const int qi = blockIdx.x * 128 + tid;

    const float SCALE = 0.125f * 1.44269504088896340736f;

    const float* qptr = Q + ((size_t)bh * Tc + qi) * Dc;
    float q[64];
#pragma unroll
    for (int d = 0; d < 64; d += 4) {
        float4 v4 = *(const float4*)(qptr + d);
        q[d + 0] = v4.x * SCALE;
        q[d + 1] = v4.y * SCALE;
        q[d + 2] = v4.z * SCALE;
        q[d + 3] = v4.w * SCALE;
    }

    float acc[64];
#pragma unroll
    for (int d = 0; d < 64; d++) acc[d] = 0.0f;
    float m = neg_inf();
    float l = 0.0f;

    const int limit = blockIdx.x * 128 + 128;
    const float* kbase = K + (size_t)bh * Tc * Dc;
    const float* vbase = V + (size_t)bh * Tc * Dc;

    for (int t0 = 0; t0 < limit; t0 += 32) {
        __syncthreads();
#pragma unroll
        for (int c2 = 0; c2 < 4; c2++) {
            const int lin = c2 * 512 + tid * 4;
            const int row = lin >> 6;
            const int col = lin & 63;
            *(float4*)&Ks[row][col] =
                *(const float4*)(kbase + (size_t)(t0 + row) * Dc + col);
            *(float4*)&Vs[row][col] =
                *(const float4*)(vbase + (size_t)(t0 + row) * Dc + col);
        }
        __syncthreads();

        float s[32];
        float mt = m;
#pragma unroll 4
        for (int j = 0; j < 32; j++) {
            const float4* kr = (const float4*)Ks[j];
            float s0 = 0.f, s1 = 0.f, s2 = 0.f, s3 = 0.f;
#pragma unroll
            for (int d4 = 0; d4 < 16; d4++) {
                float4 kv = kr[d4];
                s0 = fmaf(q[d4 * 4 + 0], kv.x, s0);
                s1 = fmaf(q[d4 * 4 + 1], kv.y, s1);
                s2 = fmaf(q[d4 * 4 + 2], kv.z, s2);
                s3 = fmaf(q[d4 * 4 + 3], kv.w, s3);
            }
            float sum = (s0 + s1) + (s2 + s3);
            s[j] = (t0 + j <= qi) ? sum : neg_inf();
            mt = fmaxf(mt, s[j]);
        }

        const float alpha = exp2f(m - mt);
        m = mt;
        l *= alpha;
#pragma unroll
        for (int d = 0; d < 64; d++) acc[d] *= alpha;

#pragma unroll 4
        for (int j = 0; j < 32; j++) {
            const float p = exp2f(s[j] - mt);
            l += p;
            const float4* vr = (const float4*)Vs[j];
#pragma unroll
            for (int d4 = 0; d4 < 16; d4++) {
                float4 vv = vr[d4];
                acc[d4 * 4 + 0] = fmaf(p, vv.x, acc[d4 * 4 + 0]);
                acc[d4 * 4 + 1] = fmaf(p, vv.y, acc[d4 * 4 + 1]);
                acc[d4 * 4 + 2] = fmaf(p, vv.z, acc[d4 * 4 + 2]);
                acc[d4 * 4 + 3] = fmaf(p, vv.w, acc[d4 * 4 + 3]);
            }
        }
    }

    const float inv = 1.0f / l;
    float* optr = O + ((size_t)b * Tc + qi) * Cc + h * Dc;
#pragma unroll
    for (int d = 0; d < 64; d += 4) {
        float4 o4;
        o4.x = tf32r(acc[d + 0] * inv);
        o4.y = tf32r(acc[d + 1] * inv);
        o4.z = tf32r(acc[d + 2] * inv);
        o4.w = tf32r(acc[d + 3] * inv);
        *(float4*)(optr + d) = o4;
    }
}

// ---------------------------------------------------------------------------
// Host launcher
// ---------------------------------------------------------------------------
extern "C" void kernel_launch(void* const* d_in, const int* in_sizes, int n_in,
                              void* d_out, int out_size)
{
    const float* x    = (const float*)d_in[0];
    // d_in[1] = mask (static causal — unused)
    const float* Wqkv = (const float*)d_in[2];
    const float* bqkv = (const float*)d_in[3];
    const float* Wout = (const float*)d_in[4];
    const float* bout = (const float*)d_in[5];
    float* out = (float*)d_out;

    float* qkv = nullptr;
    float* att = nullptr;
    float* xr = nullptr;
    float* wqkvT = nullptr;
    float* woutT = nullptr;
    cudaGetSymbolAddress((void**)&qkv, g_qkv);
    cudaGetSymbolAddress((void**)&att, g_att);
    cudaGetSymbolAddress((void**)&xr, g_xr);
    cudaGetSymbolAddress((void**)&wqkvT, g_wqkvT);
    cudaGetSymbolAddress((void**)&woutT, g_woutT);

    const int M = Bc * Tc;       // 8192

    // 0) prep: round x to tf32; transpose+round weights -> K-major [N, K]
    {
        const int nx = M * Cc;
        round_kernel<<<nx / (256 * 4), 256>>>(x, xr, nx);
        dim3 g1(3 * Cc / 32, Cc / 32);
        transpose_kernel<<<g1, 256>>>(Wqkv, wqkvT, Cc, 3 * Cc);
        dim3 g2(Cc / 32, Cc / 32);
        transpose_kernel<<<g2, 256>>>(Wout, woutT, Cc, Cc);
    }

    // 1) QKV GEMM + bias (tf32 mma.sync), scattered into [s][B][H][T][D]
    {
        dim3 grid((3 * Cc) / 128, M / 128);   // (24, 64)
        gemm_mma<1><<<grid, 256>>>(xr, wqkvT, bqkv, nullptr, M, 3 * Cc, Cc);
    }

    // 2) causal flash attention -> g_att [B,T,C] (tf32-rounded)
    {
        const float* Qp = qkv;
        const float* Kp = qkv + BHTD;
        const float* Vp = qkv + 2 * BHTD;
        dim3 grid(Tc / 128, Bc * Hc);         // (16, 64)
        attn_kernel<<<grid, 128>>>(Qp, Kp, Vp, att);
    }

    // 3) output projection + bias (tf32 mma.sync) -> d_out
    {
        dim3 grid(Cc / 128, M / 128);         // (8, 64)
        gemm_mma<0><<<grid, 256>>>(att, woutT, bout, out, M, Cc, Cc);
    }
}

// round 8
// speedup vs baseline: 3.6254x; 2.2896x over previous
#include <cuda_runtime.h>
#include <cstdint>

// Problem constants
#define Bc 4
#define Tc 2048
#define Cc 1024
#define Hc 16
#define Dc 64
#define BHTD ((size_t)Bc * Hc * Tc * Dc)   // 8388608

// Scratch (static device globals — no allocation allowed)
__device__ float g_qkv[3 * Bc * Hc * Tc * Dc];        // [s][B][H][T][D] tf32-rounded
__device__ float g_att[(size_t)Bc * Tc * Cc];          // [B,T,C] (tf32-rounded)
__device__ float g_xr[(size_t)Bc * Tc * Cc];           // x, tf32-rounded
__device__ float g_wqkvT[3 * Cc * Cc];                 // Wqkv^T [3072,1024], tf32-rounded
__device__ float g_woutT[(size_t)Cc * Cc];             // Wout^T [1024,1024], tf32-rounded

__device__ __forceinline__ float neg_inf() { return __int_as_float(0xff800000); }

__device__ __forceinline__ float tf32r(float x) {
    float y;
    asm("cvt.rna.tf32.f32 %0, %1;" : "=f"(y) : "f"(x));
    return y;
}

__device__ __forceinline__ uint32_t smem_u32(const void* p) {
    uint32_t a;
    asm("{ .reg .u64 t; cvta.to.shared.u64 t, %1; cvt.u32.u64 %0, t; }"
        : "=r"(a) : "l"(p));
    return a;
}

__device__ __forceinline__ void cp_async16(uint32_t smem_dst, const void* gsrc) {
    asm volatile("cp.async.cg.shared.global [%0], [%1], 16;"
                 :: "r"(smem_dst), "l"(gsrc) : "memory");
}
__device__ __forceinline__ void cp_async_commit() {
    asm volatile("cp.async.commit_group;" ::: "memory");
}
__device__ __forceinline__ void cp_async_wait0() {
    asm volatile("cp.async.wait_group 0;" ::: "memory");
}

// mma.sync m16n8k8 tf32 (A row-major, B col-major, fp32 accum)
__device__ __forceinline__ void mma_tf32(float* d, const uint32_t* a, const uint32_t* b) {
    asm volatile(
        "mma.sync.aligned.m16n8k8.row.col.f32.tf32.tf32.f32 "
        "{%0,%1,%2,%3}, {%4,%5,%6,%7}, {%8,%9}, {%0,%1,%2,%3};"
        : "+f"(d[0]), "+f"(d[1]), "+f"(d[2]), "+f"(d[3])
        : "r"(a[0]), "r"(a[1]), "r"(a[2]), "r"(a[3]), "r"(b[0]), "r"(b[1]));
}

// ---------------------------------------------------------------------------
// Elementwise tf32 rounding
// ---------------------------------------------------------------------------
__global__ __launch_bounds__(256)
void round_kernel(const float* __restrict__ in, float* __restrict__ out, int n)
{
    const int i = (blockIdx.x * 256 + threadIdx.x) * 4;
    if (i < n) {
        float4 v = *(const float4*)(in + i);
        v.x = tf32r(v.x); v.y = tf32r(v.y); v.z = tf32r(v.z); v.w = tf32r(v.w);
        *(float4*)(out + i) = v;
    }
}

// ---------------------------------------------------------------------------
// Transpose + tf32 round: out[c][r] = rna_tf32(in[r][c])  (R rows, C cols)
// ---------------------------------------------------------------------------
__global__ __launch_bounds__(256)
void transpose_kernel(const float* __restrict__ in, float* __restrict__ out,
                      int R, int C)
{
    __shared__ float tile[32][33];
    const int c0 = blockIdx.x * 32;
    const int r0 = blockIdx.y * 32;
    const int x = threadIdx.x & 31;
    const int y = threadIdx.x >> 5;
#pragma unroll
    for (int i = 0; i < 32; i += 8)
        tile[y + i][x] = in[(size_t)(r0 + y + i) * C + c0 + x];
    __syncthreads();
#pragma unroll
    for (int i = 0; i < 32; i += 8)
        out[(size_t)(c0 + y + i) * R + r0 + x] = tf32r(tile[x][y + i]);
}

// ---------------------------------------------------------------------------
// tf32 mma.sync GEMM:  C[M,N] = A[M,K] @ Bt[N,K]^T + bias
// CTA 128x128, 8 warps (2m x 4n), warp tile 64x32, BK=16, double-buffered.
// MODE 0: plain write.  MODE 1: scatter into g_qkv (tf32-rounded).
// ---------------------------------------------------------------------------
#define PAD 20

template <int MODE>
__global__ __launch_bounds__(256)
void gemm_mma(const float* __restrict__ A, const float* __restrict__ Bt,
              const float* __restrict__ bias, float* __restrict__ Cout,
              int M, int N, int K)
{
    __shared__ float As[2][128 * PAD];
    __shared__ float Bs[2][128 * PAD];

    const int tid = threadIdx.x;
    const int wid = tid >> 5;
    const int lid = tid & 31;
    const int g   = lid >> 2;
    const int tg  = lid & 3;
    const int wm  = (wid >> 2) * 64;
    const int wn  = (wid & 3) * 32;

    const int m0 = blockIdx.y * 128;
    const int n0 = blockIdx.x * 128;
    const int KT = K >> 4;

    const int lrow0 = tid >> 2;
    const int lrow1 = (tid + 256) >> 2;
    const int lc16  = tid & 3;

    float acc[4][4][4];
#pragma unroll
    for (int i = 0; i < 4; i++)
#pragma unroll
        for (int j = 0; j < 4; j++)
#pragma unroll
            for (int r = 0; r < 4; r++) acc[i][j][r] = 0.0f;

    auto load_stage = [&](int kt, int buf) {
        const float* ga = A  + (size_t)m0 * K + kt * 16;
        const float* gb = Bt + (size_t)n0 * K + kt * 16;
        const uint32_t sa = smem_u32(&As[buf][0]);
        const uint32_t sb = smem_u32(&Bs[buf][0]);
        cp_async16(sa + (lrow0 * PAD + lc16 * 4) * 4, ga + (size_t)lrow0 * K + lc16 * 4);
        cp_async16(sa + (lrow1 * PAD + lc16 * 4) * 4, ga + (size_t)lrow1 * K + lc16 * 4);
        cp_async16(sb + (lrow0 * PAD + lc16 * 4) * 4, gb + (size_t)lrow0 * K + lc16 * 4);
        cp_async16(sb + (lrow1 * PAD + lc16 * 4) * 4, gb + (size_t)lrow1 * K + lc16 * 4);
    };

    load_stage(0, 0);
    cp_async_commit();

    for (int kt = 0; kt < KT; kt++) {
        const int buf = kt & 1;
        cp_async_wait0();
        __syncthreads();
        if (kt + 1 < KT) {
            load_stage(kt + 1, (kt + 1) & 1);
            cp_async_commit();
        }

#pragma unroll
        for (int ks = 0; ks < 2; ks++) {
            uint32_t af[4][4], bf[4][2];
#pragma unroll
            for (int i = 0; i < 4; i++) {
                const uint32_t* p = (const uint32_t*)
                    &As[buf][(wm + i * 16 + g) * PAD + ks * 8 + tg];
                af[i][0] = p[0];
                af[i][1] = p[8 * PAD];
                af[i][2] = p[4];
                af[i][3] = p[8 * PAD + 4];
            }
#pragma unroll
            for (int j = 0; j < 4; j++) {
                const uint32_t* p = (const uint32_t*)
                    &Bs[buf][(wn + j * 8 + g) * PAD + ks * 8 + tg];
                bf[j][0] = p[0];
                bf[j][1] = p[4];
            }
#pragma unroll
            for (int i = 0; i < 4; i++)
#pragma unroll
                for (int j = 0; j < 4; j++)
                    mma_tf32(acc[i][j], af[i], bf[j]);
        }
        __syncthreads();
    }

#pragma unroll
    for (int i = 0; i < 4; i++) {
        const int r0 = m0 + wm + i * 16 + g;
        const int r1 = r0 + 8;
#pragma unroll
        for (int j = 0; j < 4; j++) {
            const int c = n0 + wn + j * 8 + 2 * tg;
            const float2 bv = *(const float2*)(bias + c);
            float2 v0, v1;
            v0.x = acc[i][j][0] + bv.x;  v0.y = acc[i][j][1] + bv.y;
            v1.x = acc[i][j][2] + bv.x;  v1.y = acc[i][j][3] + bv.y;
            if (MODE == 0) {
                *(float2*)(Cout + (size_t)r0 * N + c) = v0;
                *(float2*)(Cout + (size_t)r1 * N + c) = v1;
            } else {
                // qkv feeds tf32 attention mmas -> round at the source
                v0.x = tf32r(v0.x); v0.y = tf32r(v0.y);
                v1.x = tf32r(v1.x); v1.y = tf32r(v1.y);
                const int sidx = c >> 10;
                const int rem  = c & (Cc - 1);
                const int h    = rem >> 6;
                const int dd   = rem & (Dc - 1);
                const int b0i = r0 >> 11, t0i = r0 & (Tc - 1);
                const int b1i = r1 >> 11, t1i = r1 & (Tc - 1);
                const size_t base = (size_t)(sidx * Bc) * Hc;
                const size_t d0 = (((base + (size_t)b0i * Hc + h) * Tc + t0i) << 6) + dd;
                const size_t d1 = (((base + (size_t)b1i * Hc + h) * Tc + t1i) << 6) + dd;
                *(float2*)&g_qkv[d0] = v0;
                *(float2*)&g_qkv[d1] = v1;
            }
        }
    }
}

// ---------------------------------------------------------------------------
// Tensor-core causal flash attention (tf32 mma.sync).
// CTA: 64 queries of one (b,h); 4 warps x 16 rows. Key blocks of 64.
//   S = Q K^T : A-frags = Q rows (registers), B-frags = K rows (smem, K-major)
//   P V       : A-frags = P via per-warp smem round-trip, B-frags = V smem
// Smem pads: Ks 68 (banks 4g+tg), Vs 72 (banks 8tg+g), Ps 68 — all conflict-free.
// ---------------------------------------------------------------------------
#define KS_ST 68
#define VS_ST 72
#define PS_ST 68
#define ATT_SMEM ((64 * KS_ST + 64 * VS_ST + 4 * 16 * PS_ST) * 4)   // 53248 B

__global__ __launch_bounds__(128)
void attn_mma_kernel(const float* __restrict__ Q, const float* __restrict__ K,
                     const float* __restrict__ V, float* __restrict__ O)
{
    extern __shared__ float sm[];
    float* Ks = sm;                       // [64][68]
    float* Vs = sm + 64 * KS_ST;          // [64][72]
    float* Ps = Vs + 64 * VS_ST;          // [4][16][68]

    const int tid = threadIdx.x;
    const int wid = tid >> 5;
    const int lid = tid & 31;
    const int g   = lid >> 2;
    const int tg  = lid & 3;
    const int bh  = blockIdx.y;
    const int b   = bh >> 4;
    const int h   = bh & 15;
    const int qb  = gridDim.x - 1 - blockIdx.x;   // heavy blocks first
    const int q0  = qb * 64;

    const float SCALE = 0.125f * 1.44269504088896340736f;

    // Q fragments, register-resident (16 rows x 64 cols per warp)
    const float* qbase = Q + ((size_t)bh * Tc + q0 + wid * 16) * Dc;
    uint32_t qf[8][4];
#pragma unroll
    for (int k = 0; k < 8; k++) {
        qf[k][0] = __float_as_uint(tf32r(qbase[(size_t)g * Dc       + 8 * k + tg]     * SCALE));
        qf[k][1] = __float_as_uint(tf32r(qbase[(size_t)(g + 8) * Dc + 8 * k + tg]     * SCALE));
        qf[k][2] = __float_as_uint(tf32r(qbase[(size_t)g * Dc       + 8 * k + tg + 4] * SCALE));
        qf[k][3] = __float_as_uint(tf32r(qbase[(size_t)(g + 8) * Dc + 8 * k + tg + 4] * SCALE));
    }

    float o[8][4];
#pragma unroll
    for (int nt = 0; nt < 8; nt++)
#pragma unroll
        for (int r = 0; r < 4; r++) o[nt][r] = 0.0f;
    float m0 = neg_inf(), m1 = neg_inf(), l0 = 0.0f, l1 = 0.0f;

    const float* kg = K + (size_t)bh * Tc * Dc;
    const float* vg = V + (size_t)bh * Tc * Dc;
    const uint32_t ksu = smem_u32(Ks);
    const uint32_t vsu = smem_u32(Vs);
    float* Pw = Ps + wid * 16 * PS_ST;

    const int lrow = tid >> 4;        // base loader row (chunk layout below)
    (void)lrow;

    for (int t0 = 0; t0 <= q0; t0 += 64) {
        __syncthreads();
        // load K,V tiles: 1024 16B-chunks each, 8 per thread per operand
#pragma unroll
        for (int i = 0; i < 8; i++) {
            const int c = tid + i * 128;
            const int row = c >> 4;
            const int c16 = c & 15;
            cp_async16(ksu + (row * KS_ST + c16 * 4) * 4,
                       kg + (size_t)(t0 + row) * Dc + c16 * 4);
            cp_async16(vsu + (row * VS_ST + c16 * 4) * 4,
                       vg + (size_t)(t0 + row) * Dc + c16 * 4);
        }
        cp_async_commit();
        cp_async_wait0();
        __syncthreads();

        // S = Q K^T   (16 x 64 per warp)
        float s[8][4];
#pragma unroll
        for (int nt = 0; nt < 8; nt++) {
            s[nt][0] = s[nt][1] = s[nt][2] = s[nt][3] = 0.0f;
#pragma unroll
            for (int k = 0; k < 8; k++) {
                uint32_t bf[2];
                const uint32_t* p = (const uint32_t*)&Ks[(nt * 8 + g) * KS_ST + 8 * k + tg];
                bf[0] = p[0];
                bf[1] = p[4];
                mma_tf32(s[nt], qf[k], bf);
            }
        }

        // causal mask on the diagonal block
        if (t0 == q0) {
            const int r0 = wid * 16 + g;
            const int r1 = r0 + 8;
#pragma unroll
            for (int nt = 0; nt < 8; nt++) {
                const int c0i = nt * 8 + 2 * tg;
                if (c0i     > r0) s[nt][0] = neg_inf();
                if (c0i + 1 > r0) s[nt][1] = neg_inf();
                if (c0i     > r1) s[nt][2] = neg_inf();
                if (c0i + 1 > r1) s[nt][3] = neg_inf();
            }
        }

        // row max (local -> quad bfly)
        float mt0 = m0, mt1 = m1;
#pragma unroll
        for (int nt = 0; nt < 8; nt++) {
            mt0 = fmaxf(mt0, fmaxf(s[nt][0], s[nt][1]));
            mt1 = fmaxf(mt1, fmaxf(s[nt][2], s[nt][3]));
        }
        mt0 = fmaxf(mt0, __shfl_xor_sync(0xffffffffu, mt0, 1));
        mt0 = fmaxf(mt0, __shfl_xor_sync(0xffffffffu, mt0, 2));
        mt1 = fmaxf(mt1, __shfl_xor_sync(0xffffffffu, mt1, 1));
        mt1 = fmaxf(mt1, __shfl_xor_sync(0xffffffffu, mt1, 2));

        const float a0 = exp2f(m0 - mt0);
        const float a1 = exp2f(m1 - mt1);
        m0 = mt0; m1 = mt1;
        l0 *= a0;  l1 *= a1;
#pragma unroll
        for (int nt = 0; nt < 8; nt++) {
            o[nt][0] *= a0; o[nt][1] *= a0;
            o[nt][2] *= a1; o[nt][3] *= a1;
        }

        // P = exp2(S - m), accumulate l, stash P (tf32-rounded) in warp smem
#pragma unroll
        for (int nt = 0; nt < 8; nt++) {
            float p00 = exp2f(s[nt][0] - mt0);
            float p01 = exp2f(s[nt][1] - mt0);
            float p10 = exp2f(s[nt][2] - mt1);
            float p11 = exp2f(s[nt][3] - mt1);
            p00 = tf32r(p00); p01 = tf32r(p01);
            p10 = tf32r(p10); p11 = tf32r(p11);
            l0 += p00 + p01;
            l1 += p10 + p11;
            *(float2*)&Pw[g * PS_ST + nt * 8 + 2 * tg]       = make_float2(p00, p01);
            *(float2*)&Pw[(g + 8) * PS_ST + nt * 8 + 2 * tg] = make_float2(p10, p11);
        }
        __syncwarp();

        // O += P V
#pragma unroll
        for (int k = 0; k < 8; k++) {
            uint32_t af[4];
            af[0] = *(const uint32_t*)&Pw[g * PS_ST       + 8 * k + tg];
            af[1] = *(const uint32_t*)&Pw[(g + 8) * PS_ST + 8 * k + tg];
            af[2] = *(const uint32_t*)&Pw[g * PS_ST       + 8 * k + tg + 4];
            af[3] = *(const uint32_t*)&Pw[(g + 8) * PS_ST + 8 * k + tg + 4];
#pragma unroll
            for (int nt = 0; nt < 8; nt++) {
                uint32_t bf[2];
                bf[0] = *(const uint32_t*)&Vs[(8 * k + tg) * VS_ST     + nt * 8 + g];
                bf[1] = *(const uint32_t*)&Vs[(8 * k + tg + 4) * VS_ST + nt * 8 + g];
                mma_tf32(o[nt], af, bf);
            }
        }
    }

    // final l reduce + normalize + store (tf32-rounded: feeds tf32 GEMM2)
    l0 += __shfl_xor_sync(0xffffffffu, l0, 1);
    l0 += __shfl_xor_sync(0xffffffffu, l0, 2);
    l1 += __shfl_xor_sync(0xffffffffu, l1, 1);
    l1 += __shfl_xor_sync(0xffffffffu, l1, 2);
    const float inv0 = 1.0f / l0;
    const float inv1 = 1.0f / l1;

    const int row0 = q0 + wid * 16 + g;
    const int row1 = row0 + 8;
    float* ob0 = O + ((size_t)b * Tc + row0) * Cc + h * Dc;
    float* ob1 = O + ((size_t)b * Tc + row1) * Cc + h * Dc;
#pragma unroll
    for (int nt = 0; nt < 8; nt++) {
        const int c = nt * 8 + 2 * tg;
        *(float2*)(ob0 + c) = make_float2(tf32r(o[nt][0] * inv0), tf32r(o[nt][1] * inv0));
        *(float2*)(ob1 + c) = make_float2(tf32r(o[nt][2] * inv1), tf32r(o[nt][3] * inv1));
    }
}

// ---------------------------------------------------------------------------
// Host launcher
// ---------------------------------------------------------------------------
extern "C" void kernel_launch(void* const* d_in, const int* in_sizes, int n_in,
                              void* d_out, int out_size)
{
    const float* x    = (const float*)d_in[0];
    // d_in[1] = mask (static causal — unused)
    const float* Wqkv = (const float*)d_in[2];
    const float* bqkv = (const float*)d_in[3];
    const float* Wout = (const float*)d_in[4];
    const float* bout = (const float*)d_in[5];
    float* out = (float*)d_out;

    float* qkv = nullptr;
    float* att = nullptr;
    float* xr = nullptr;
    float* wqkvT = nullptr;
    float* woutT = nullptr;
    cudaGetSymbolAddress((void**)&qkv, g_qkv);
    cudaGetSymbolAddress((void**)&att, g_att);
    cudaGetSymbolAddress((void**)&xr, g_xr);
    cudaGetSymbolAddress((void**)&wqkvT, g_wqkvT);
    cudaGetSymbolAddress((void**)&woutT, g_woutT);

    cudaFuncSetAttribute(attn_mma_kernel,
                         cudaFuncAttributeMaxDynamicSharedMemorySize, ATT_SMEM);

    const int M = Bc * Tc;       // 8192

    // 0) prep: round x; transpose+round weights -> K-major [N, K]
    {
        const int nx = M * Cc;
        round_kernel<<<nx / (256 * 4), 256>>>(x, xr, nx);
        dim3 g1(3 * Cc / 32, Cc / 32);
        transpose_kernel<<<g1, 256>>>(Wqkv, wqkvT, Cc, 3 * Cc);
        dim3 g2(Cc / 32, Cc / 32);
        transpose_kernel<<<g2, 256>>>(Wout, woutT, Cc, Cc);
    }

    // 1) QKV GEMM + bias (tf32 mma.sync) -> g_qkv [s][B][H][T][D], rounded
    {
        dim3 grid((3 * Cc) / 128, M / 128);   // (24, 64)
        gemm_mma<1><<<grid, 256>>>(xr, wqkvT, bqkv, nullptr, M, 3 * Cc, Cc);
    }

    // 2) causal flash attention (tf32 mma.sync) -> g_att [B,T,C], rounded
    {
        const float* Qp = qkv;
        const float* Kp = qkv + BHTD;
        const float* Vp = qkv + 2 * BHTD;
        dim3 grid(Tc / 64, Bc * Hc);          // (32, 64)
        attn_mma_kernel<<<grid, 128, ATT_SMEM>>>(Qp, Kp, Vp, att);
    }

    // 3) output projection + bias (tf32 mma.sync) -> d_out
    {
        dim3 grid(Cc / 128, M / 128);         // (8, 64)
        gemm_mma<0><<<grid, 256>>>(att, woutT, bout, out, M, Cc, Cc);
    }
}

// round 9
// speedup vs baseline: 4.0116x; 1.1065x over previous
#include <cuda_runtime.h>
#include <cstdint>

// Problem constants
#define Bc 4
#define Tc 2048
#define Cc 1024
#define Hc 16
#define Dc 64
#define BHTD ((size_t)Bc * Hc * Tc * Dc)   // 8388608

// Scratch (static device globals — no allocation allowed)
__device__ float g_qkv[3 * Bc * Hc * Tc * Dc];        // [s][B][H][T][D] tf32-rounded
__device__ float g_att[(size_t)Bc * Tc * Cc];          // [B,T,C] (tf32-rounded)
__device__ float g_xr[(size_t)Bc * Tc * Cc];           // x, tf32-rounded
__device__ float g_wqkvT[3 * Cc * Cc];                 // Wqkv^T [3072,1024], tf32-rounded
__device__ float g_woutT[(size_t)Cc * Cc];             // Wout^T [1024,1024], tf32-rounded

__device__ __forceinline__ float neg_inf() { return __int_as_float(0xff800000); }

__device__ __forceinline__ float tf32r(float x) {
    float y;
    asm("cvt.rna.tf32.f32 %0, %1;" : "=f"(y) : "f"(x));
    return y;
}

__device__ __forceinline__ uint32_t smem_u32(const void* p) {
    uint32_t a;
    asm("{ .reg .u64 t; cvta.to.shared.u64 t, %1; cvt.u32.u64 %0, t; }"
        : "=r"(a) : "l"(p));
    return a;
}

__device__ __forceinline__ void cp_async16(uint32_t smem_dst, const void* gsrc) {
    asm volatile("cp.async.cg.shared.global [%0], [%1], 16;"
                 :: "r"(smem_dst), "l"(gsrc) : "memory");
}
__device__ __forceinline__ void cp_async_commit() {
    asm volatile("cp.async.commit_group;" ::: "memory");
}
__device__ __forceinline__ void cp_async_wait0() {
    asm volatile("cp.async.wait_group 0;" ::: "memory");
}

// mma.sync m16n8k8 tf32 (A row-major, B col-major, fp32 accum)
__device__ __forceinline__ void mma_tf32(float* d, const uint32_t* a, const uint32_t* b) {
    asm volatile(
        "mma.sync.aligned.m16n8k8.row.col.f32.tf32.tf32.f32 "
        "{%0,%1,%2,%3}, {%4,%5,%6,%7}, {%8,%9}, {%0,%1,%2,%3};"
        : "+f"(d[0]), "+f"(d[1]), "+f"(d[2]), "+f"(d[3])
        : "r"(a[0]), "r"(a[1]), "r"(a[2]), "r"(a[3]), "r"(b[0]), "r"(b[1]));
}

// ---------------------------------------------------------------------------
// Elementwise tf32 rounding
// ---------------------------------------------------------------------------
__global__ __launch_bounds__(256)
void round_kernel(const float* __restrict__ in, float* __restrict__ out, int n)
{
    const int i = (blockIdx.x * 256 + threadIdx.x) * 4;
    if (i < n) {
        float4 v = *(const float4*)(in + i);
        v.x = tf32r(v.x); v.y = tf32r(v.y); v.z = tf32r(v.z); v.w = tf32r(v.w);
        *(float4*)(out + i) = v;
    }
}

// ---------------------------------------------------------------------------
// Transpose + tf32 round: out[c][r] = rna_tf32(in[r][c])  (R rows, C cols)
// ---------------------------------------------------------------------------
__global__ __launch_bounds__(256)
void transpose_kernel(const float* __restrict__ in, float* __restrict__ out,
                      int R, int C)
{
    __shared__ float tile[32][33];
    const int c0 = blockIdx.x * 32;
    const int r0 = blockIdx.y * 32;
    const int x = threadIdx.x & 31;
    const int y = threadIdx.x >> 5;
#pragma unroll
    for (int i = 0; i < 32; i += 8)
        tile[y + i][x] = in[(size_t)(r0 + y + i) * C + c0 + x];
    __syncthreads();
#pragma unroll
    for (int i = 0; i < 32; i += 8)
        out[(size_t)(c0 + y + i) * R + r0 + x] = tf32r(tile[x][y + i]);
}

// ---------------------------------------------------------------------------
// tf32 mma.sync GEMM:  C[M,N] = A[M,K] @ Bt[N,K]^T + bias
// CTA 128x128, 128 threads = 4 warps (2m x 2n), warp tile 64x64, BK=16,
// double-buffered cp.async. 32 MMAs : 32 LDS per warp per k8-step.
// MODE 0: plain write.  MODE 1: scatter into g_qkv (tf32-rounded).
// ---------------------------------------------------------------------------
#define PAD 20

template <int MODE>
__global__ __launch_bounds__(128)
void gemm_mma(const float* __restrict__ A, const float* __restrict__ Bt,
              const float* __restrict__ bias, float* __restrict__ Cout,
              int M, int N, int K)
{
    __shared__ float As[2][128 * PAD];
    __shared__ float Bs[2][128 * PAD];

    const int tid = threadIdx.x;
    const int wid = tid >> 5;            // 0..3
    const int lid = tid & 31;
    const int g   = lid >> 2;
    const int tg  = lid & 3;
    const int wm  = (wid >> 1) * 64;     // warp m offset
    const int wn  = (wid & 1) * 64;      // warp n offset

    const int m0 = blockIdx.y * 128;
    const int n0 = blockIdx.x * 128;
    const int KT = K >> 4;

    float acc[4][8][4];
#pragma unroll
    for (int i = 0; i < 4; i++)
#pragma unroll
        for (int j = 0; j < 8; j++)
#pragma unroll
            for (int r = 0; r < 4; r++) acc[i][j][r] = 0.0f;

    // loader: 512 16B chunks per operand, 4 per thread per operand
    auto load_stage = [&](int kt, int buf) {
        const float* ga = A  + (size_t)m0 * K + kt * 16;
        const float* gb = Bt + (size_t)n0 * K + kt * 16;
        const uint32_t sa = smem_u32(&As[buf][0]);
        const uint32_t sb = smem_u32(&Bs[buf][0]);
#pragma unroll
        for (int i = 0; i < 4; i++) {
            const int c = tid + i * 128;          // 0..511
            const int row = c >> 2;               // 0..127
            const int c16 = c & 3;                // 16B chunk in row
            cp_async16(sa + (row * PAD + c16 * 4) * 4, ga + (size_t)row * K + c16 * 4);
            cp_async16(sb + (row * PAD + c16 * 4) * 4, gb + (size_t)row * K + c16 * 4);
        }
    };

    load_stage(0, 0);
    cp_async_commit();

    for (int kt = 0; kt < KT; kt++) {
        const int buf = kt & 1;
        cp_async_wait0();
        __syncthreads();
        if (kt + 1 < KT) {
            load_stage(kt + 1, (kt + 1) & 1);
            cp_async_commit();
        }

#pragma unroll
        for (int ks = 0; ks < 2; ks++) {
            uint32_t af[4][4], bf[8][2];
#pragma unroll
            for (int i = 0; i < 4; i++) {
                const uint32_t* p = (const uint32_t*)
                    &As[buf][(wm + i * 16 + g) * PAD + ks * 8 + tg];
                af[i][0] = p[0];
                af[i][1] = p[8 * PAD];
                af[i][2] = p[4];
                af[i][3] = p[8 * PAD + 4];
            }
#pragma unroll
            for (int j = 0; j < 8; j++) {
                const uint32_t* p = (const uint32_t*)
                    &Bs[buf][(wn + j * 8 + g) * PAD + ks * 8 + tg];
                bf[j][0] = p[0];
                bf[j][1] = p[4];
            }
#pragma unroll
            for (int i = 0; i < 4; i++)
#pragma unroll
                for (int j = 0; j < 8; j++)
                    mma_tf32(acc[i][j], af[i], bf[j]);
        }
        __syncthreads();
    }

    // epilogue: c0,c1 -> (row g, cols 2tg,2tg+1); c2,c3 -> row g+8
#pragma unroll
    for (int i = 0; i < 4; i++) {
        const int r0 = m0 + wm + i * 16 + g;
        const int r1 = r0 + 8;
#pragma unroll
        for (int j = 0; j < 8; j++) {
            const int c = n0 + wn + j * 8 + 2 * tg;
            const float2 bv = *(const float2*)(bias + c);
            float2 v0, v1;
            v0.x = acc[i][j][0] + bv.x;  v0.y = acc[i][j][1] + bv.y;
            v1.x = acc[i][j][2] + bv.x;  v1.y = acc[i][j][3] + bv.y;
            if (MODE == 0) {
                *(float2*)(Cout + (size_t)r0 * N + c) = v0;
                *(float2*)(Cout + (size_t)r1 * N + c) = v1;
            } else {
                // qkv feeds tf32 attention mmas -> round at the source
                v0.x = tf32r(v0.x); v0.y = tf32r(v0.y);
                v1.x = tf32r(v1.x); v1.y = tf32r(v1.y);
                const int sidx = c >> 10;
                const int rem  = c & (Cc - 1);
                const int h    = rem >> 6;
                const int dd   = rem & (Dc - 1);
                const int b0i = r0 >> 11, t0i = r0 & (Tc - 1);
                const int b1i = r1 >> 11, t1i = r1 & (Tc - 1);
                const size_t base = (size_t)(sidx * Bc) * Hc;
                const size_t d0 = (((base + (size_t)b0i * Hc + h) * Tc + t0i) << 6) + dd;
                const size_t d1 = (((base + (size_t)b1i * Hc + h) * Tc + t1i) << 6) + dd;
                *(float2*)&g_qkv[d0] = v0;
                *(float2*)&g_qkv[d1] = v1;
            }
        }
    }
}

// ---------------------------------------------------------------------------
// Tensor-core causal flash attention (tf32 mma.sync).  (unchanged)
// CTA: 64 queries of one (b,h); 4 warps x 16 rows. Key blocks of 64.
// ---------------------------------------------------------------------------
#define KS_ST 68
#define VS_ST 72
#define PS_ST 68
#define ATT_SMEM ((64 * KS_ST + 64 * VS_ST + 4 * 16 * PS_ST) * 4)   // 53248 B

__global__ __launch_bounds__(128)
void attn_mma_kernel(const float* __restrict__ Q, const float* __restrict__ K,
                     const float* __restrict__ V, float* __restrict__ O)
{
    extern __shared__ float sm[];
    float* Ks = sm;                       // [64][68]
    float* Vs = sm + 64 * KS_ST;          // [64][72]
    float* Ps = Vs + 64 * VS_ST;          // [4][16][68]

    const int tid = threadIdx.x;
    const int wid = tid >> 5;
    const int lid = tid & 31;
    const int g   = lid >> 2;
    const int tg  = lid & 3;
    const int bh  = blockIdx.y;
    const int b   = bh >> 4;
    const int h   = bh & 15;
    const int qb  = gridDim.x - 1 - blockIdx.x;   // heavy blocks first
    const int q0  = qb * 64;

    const float SCALE = 0.125f * 1.44269504088896340736f;

    const float* qbase = Q + ((size_t)bh * Tc + q0 + wid * 16) * Dc;
    uint32_t qf[8][4];
#pragma unroll
    for (int k = 0; k < 8; k++) {
        qf[k][0] = __float_as_uint(tf32r(qbase[(size_t)g * Dc       + 8 * k + tg]     * SCALE));
        qf[k][1] = __float_as_uint(tf32r(qbase[(size_t)(g + 8) * Dc + 8 * k + tg]     * SCALE));
        qf[k][2] = __float_as_uint(tf32r(qbase[(size_t)g * Dc       + 8 * k + tg + 4] * SCALE));
        qf[k][3] = __float_as_uint(tf32r(qbase[(size_t)(g + 8) * Dc + 8 * k + tg + 4] * SCALE));
    }

    float o[8][4];
#pragma unroll
    for (int nt = 0; nt < 8; nt++)
#pragma unroll
        for (int r = 0; r < 4; r++) o[nt][r] = 0.0f;
    float m0 = neg_inf(), m1 = neg_inf(), l0 = 0.0f, l1 = 0.0f;

    const float* kg = K + (size_t)bh * Tc * Dc;
    const float* vg = V + (size_t)bh * Tc * Dc;
    const uint32_t ksu = smem_u32(Ks);
    const uint32_t vsu = smem_u32(Vs);
    float* Pw = Ps + wid * 16 * PS_ST;

    for (int t0 = 0; t0 <= q0; t0 += 64) {
        __syncthreads();
#pragma unroll
        for (int i = 0; i < 8; i++) {
            const int c = tid + i * 128;
            const int row = c >> 4;
            const int c16 = c & 15;
            cp_async16(ksu + (row * KS_ST + c16 * 4) * 4,
                       kg + (size_t)(t0 + row) * Dc + c16 * 4);
            cp_async16(vsu + (row * VS_ST + c16 * 4) * 4,
                       vg + (size_t)(t0 + row) * Dc + c16 * 4);
        }
        cp_async_commit();
        cp_async_wait0();
        __syncthreads();

        // S = Q K^T   (16 x 64 per warp)
        float s[8][4];
#pragma unroll
        for (int nt = 0; nt < 8; nt++) {
            s[nt][0] = s[nt][1] = s[nt][2] = s[nt][3] = 0.0f;
#pragma unroll
            for (int k = 0; k < 8; k++) {
                uint32_t bf[2];
                const uint32_t* p = (const uint32_t*)&Ks[(nt * 8 + g) * KS_ST + 8 * k + tg];
                bf[0] = p[0];
                bf[1] = p[4];
                mma_tf32(s[nt], qf[k], bf);
            }
        }

        if (t0 == q0) {
            const int r0 = wid * 16 + g;
            const int r1 = r0 + 8;
#pragma unroll
            for (int nt = 0; nt < 8; nt++) {
                const int c0i = nt * 8 + 2 * tg;
                if (c0i     > r0) s[nt][0] = neg_inf();
                if (c0i + 1 > r0) s[nt][1] = neg_inf();
                if (c0i     > r1) s[nt][2] = neg_inf();
                if (c0i + 1 > r1) s[nt][3] = neg_inf();
            }
        }

        float mt0 = m0, mt1 = m1;
#pragma unroll
        for (int nt = 0; nt < 8; nt++) {
            mt0 = fmaxf(mt0, fmaxf(s[nt][0], s[nt][1]));
            mt1 = fmaxf(mt1, fmaxf(s[nt][2], s[nt][3]));
        }
        mt0 = fmaxf(mt0, __shfl_xor_sync(0xffffffffu, mt0, 1));
        mt0 = fmaxf(mt0, __shfl_xor_sync(0xffffffffu, mt0, 2));
        mt1 = fmaxf(mt1, __shfl_xor_sync(0xffffffffu, mt1, 1));
        mt1 = fmaxf(mt1, __shfl_xor_sync(0xffffffffu, mt1, 2));

        const float a0 = exp2f(m0 - mt0);
        const float a1 = exp2f(m1 - mt1);
        m0 = mt0; m1 = mt1;
        l0 *= a0;  l1 *= a1;
#pragma unroll
        for (int nt = 0; nt < 8; nt++) {
            o[nt][0] *= a0; o[nt][1] *= a0;
            o[nt][2] *= a1; o[nt][3] *= a1;
        }

#pragma unroll
        for (int nt = 0; nt < 8; nt++) {
            float p00 = exp2f(s[nt][0] - mt0);
            float p01 = exp2f(s[nt][1] - mt0);
            float p10 = exp2f(s[nt][2] - mt1);
            float p11 = exp2f(s[nt][3] - mt1);
            p00 = tf32r(p00); p01 = tf32r(p01);
            p10 = tf32r(p10); p11 = tf32r(p11);
            l0 += p00 + p01;
            l1 += p10 + p11;
            *(float2*)&Pw[g * PS_ST + nt * 8 + 2 * tg]       = make_float2(p00, p01);
            *(float2*)&Pw[(g + 8) * PS_ST + nt * 8 + 2 * tg] = make_float2(p10, p11);
        }
        __syncwarp();

        // O += P V
#pragma unroll
        for (int k = 0; k < 8; k++) {
            uint32_t af[4];
            af[0] = *(const uint32_t*)&Pw[g * PS_ST       + 8 * k + tg];
            af[1] = *(const uint32_t*)&Pw[(g + 8) * PS_ST + 8 * k + tg];
            af[2] = *(const uint32_t*)&Pw[g * PS_ST       + 8 * k + tg + 4];
            af[3] = *(const uint32_t*)&Pw[(g + 8) * PS_ST + 8 * k + tg + 4];
#pragma unroll
            for (int nt = 0; nt < 8; nt++) {
                uint32_t bf[2];
                bf[0] = *(const uint32_t*)&Vs[(8 * k + tg) * VS_ST     + nt * 8 + g];
                bf[1] = *(const uint32_t*)&Vs[(8 * k + tg + 4) * VS_ST + nt * 8 + g];
                mma_tf32(o[nt], af, bf);
            }
        }
    }

    l0 += __shfl_xor_sync(0xffffffffu, l0, 1);
    l0 += __shfl_xor_sync(0xffffffffu, l0, 2);
    l1 += __shfl_xor_sync(0xffffffffu, l1, 1);
    l1 += __shfl_xor_sync(0xffffffffu, l1, 2);
    const float inv0 = 1.0f / l0;
    const float inv1 = 1.0f / l1;

    const int row0 = q0 + wid * 16 + g;
    const int row1 = row0 + 8;
    float* ob0 = O + ((size_t)b * Tc + row0) * Cc + h * Dc;
    float* ob1 = O + ((size_t)b * Tc + row1) * Cc + h * Dc;
#pragma unroll
    for (int nt = 0; nt < 8; nt++) {
        const int c = nt * 8 + 2 * tg;
        *(float2*)(ob0 + c) = make_float2(tf32r(o[nt][0] * inv0), tf32r(o[nt][1] * inv0));
        *(float2*)(ob1 + c) = make_float2(tf32r(o[nt][2] * inv1), tf32r(o[nt][3] * inv1));
    }
}

// ---------------------------------------------------------------------------
// Host launcher
// ---------------------------------------------------------------------------
extern "C" void kernel_launch(void* const* d_in, const int* in_sizes, int n_in,
                              void* d_out, int out_size)
{
    const float* x    = (const float*)d_in[0];
    // d_in[1] = mask (static causal — unused)
    const float* Wqkv = (const float*)d_in[2];
    const float* bqkv = (const float*)d_in[3];
    const float* Wout = (const float*)d_in[4];
    const float* bout = (const float*)d_in[5];
    float* out = (float*)d_out;

    float* qkv = nullptr;
    float* att = nullptr;
    float* xr = nullptr;
    float* wqkvT = nullptr;
    float* woutT = nullptr;
    cudaGetSymbolAddress((void**)&qkv, g_qkv);
    cudaGetSymbolAddress((void**)&att, g_att);
    cudaGetSymbolAddress((void**)&xr, g_xr);
    cudaGetSymbolAddress((void**)&wqkvT, g_wqkvT);
    cudaGetSymbolAddress((void**)&woutT, g_woutT);

    cudaFuncSetAttribute(attn_mma_kernel,
                         cudaFuncAttributeMaxDynamicSharedMemorySize, ATT_SMEM);

    const int M = Bc * Tc;       // 8192

    // 0) prep: round x; transpose+round weights -> K-major [N, K]
    {
        const int nx = M * Cc;
        round_kernel<<<nx / (256 * 4), 256>>>(x, xr, nx);
        dim3 g1(3 * Cc / 32, Cc / 32);
        transpose_kernel<<<g1, 256>>>(Wqkv, wqkvT, Cc, 3 * Cc);
        dim3 g2(Cc / 32, Cc / 32);
        transpose_kernel<<<g2, 256>>>(Wout, woutT, Cc, Cc);
    }

    // 1) QKV GEMM + bias (tf32 mma.sync) -> g_qkv [s][B][H][T][D], rounded
    {
        dim3 grid((3 * Cc) / 128, M / 128);   // (24, 64)
        gemm_mma<1><<<grid, 128>>>(xr, wqkvT, bqkv, nullptr, M, 3 * Cc, Cc);
    }

    // 2) causal flash attention (tf32 mma.sync) -> g_att [B,T,C], rounded
    {
        const float* Qp = qkv;
        const float* Kp = qkv + BHTD;
        const float* Vp = qkv + 2 * BHTD;
        dim3 grid(Tc / 64, Bc * Hc);          // (32, 64)
        attn_mma_kernel<<<grid, 128, ATT_SMEM>>>(Qp, Kp, Vp, att);
    }

    // 3) output projection + bias (tf32 mma.sync) -> d_out
    {
        dim3 grid(Cc / 128, M / 128);         // (8, 64)
        gemm_mma<0><<<grid, 128>>>(att, woutT, bout, out, M, Cc, Cc);
    }
}

// round 10
// speedup vs baseline: 4.1741x; 1.0405x over previous
#include <cuda_runtime.h>
#include <cstdint>

// Problem constants
#define Bc 4
#define Tc 2048
#define Cc 1024
#define Hc 16
#define Dc 64
#define BHTD ((size_t)Bc * Hc * Tc * Dc)   // 8388608

// Scratch (static device globals — no allocation allowed)
__device__ float g_qkv[3 * Bc * Hc * Tc * Dc];        // [s][B][H][T][D] tf32-rounded
__device__ float g_att[(size_t)Bc * Tc * Cc];          // [B,T,C] (tf32-rounded)
__device__ float g_xr[(size_t)Bc * Tc * Cc];           // x, tf32-rounded
__device__ float g_wqkvT[3 * Cc * Cc];                 // Wqkv^T [3072,1024], tf32-rounded
__device__ float g_woutT[(size_t)Cc * Cc];             // Wout^T [1024,1024], tf32-rounded

__device__ __forceinline__ float neg_inf() { return __int_as_float(0xff800000); }

__device__ __forceinline__ float tf32r(float x) {
    float y;
    asm("cvt.rna.tf32.f32 %0, %1;" : "=f"(y) : "f"(x));
    return y;
}

__device__ __forceinline__ uint32_t smem_u32(const void* p) {
    uint32_t a;
    asm("{ .reg .u64 t; cvta.to.shared.u64 t, %1; cvt.u32.u64 %0, t; }"
        : "=r"(a) : "l"(p));
    return a;
}

__device__ __forceinline__ void cp_async16(uint32_t smem_dst, const void* gsrc) {
    asm volatile("cp.async.cg.shared.global [%0], [%1], 16;"
                 :: "r"(smem_dst), "l"(gsrc) : "memory");
}
__device__ __forceinline__ void cp_async_commit() {
    asm volatile("cp.async.commit_group;" ::: "memory");
}
__device__ __forceinline__ void cp_async_wait1() {
    asm volatile("cp.async.wait_group 1;" ::: "memory");
}

// mma.sync m16n8k8 tf32 (A row-major, B col-major, fp32 accum)
__device__ __forceinline__ void mma_tf32(float* d, const uint32_t* a, const uint32_t* b) {
    asm volatile(
        "mma.sync.aligned.m16n8k8.row.col.f32.tf32.tf32.f32 "
        "{%0,%1,%2,%3}, {%4,%5,%6,%7}, {%8,%9}, {%0,%1,%2,%3};"
        : "+f"(d[0]), "+f"(d[1]), "+f"(d[2]), "+f"(d[3])
        : "r"(a[0]), "r"(a[1]), "r"(a[2]), "r"(a[3]), "r"(b[0]), "r"(b[1]));
}

// ---------------------------------------------------------------------------
// Elementwise tf32 rounding
// ---------------------------------------------------------------------------
__global__ __launch_bounds__(256)
void round_kernel(const float* __restrict__ in, float* __restrict__ out, int n)
{
    const int i = (blockIdx.x * 256 + threadIdx.x) * 4;
    if (i < n) {
        float4 v = *(const float4*)(in + i);
        v.x = tf32r(v.x); v.y = tf32r(v.y); v.z = tf32r(v.z); v.w = tf32r(v.w);
        *(float4*)(out + i) = v;
    }
}

// ---------------------------------------------------------------------------
// Transpose + tf32 round: out[c][r] = rna_tf32(in[r][c])  (R rows, C cols)
// ---------------------------------------------------------------------------
__global__ __launch_bounds__(256)
void transpose_kernel(const float* __restrict__ in, float* __restrict__ out,
                      int R, int C)
{
    __shared__ float tile[32][33];
    const int c0 = blockIdx.x * 32;
    const int r0 = blockIdx.y * 32;
    const int x = threadIdx.x & 31;
    const int y = threadIdx.x >> 5;
#pragma unroll
    for (int i = 0; i < 32; i += 8)
        tile[y + i][x] = in[(size_t)(r0 + y + i) * C + c0 + x];
    __syncthreads();
#pragma unroll
    for (int i = 0; i < 32; i += 8)
        out[(size_t)(c0 + y + i) * R + r0 + x] = tf32r(tile[x][y + i]);
}

// ---------------------------------------------------------------------------
// tf32 mma.sync GEMM:  C[M,N] = A[M,K] @ Bt[N,K]^T + bias
// CTA 128x128, 4 warps (2m x 2n), warp tile 64x64, BK=16.
// 3-stage cp.async pipeline (prefetch distance 2), ONE syncthreads per BK step.
// MODE 0: plain write.  MODE 1: scatter into g_qkv (tf32-rounded).
// ---------------------------------------------------------------------------
#define PAD 20
#define GSTG (128 * PAD)                       // floats per operand per stage
#define GEMM_SMEM (2 * 3 * GSTG * 4)           // 61440 bytes

template <int MODE>
__global__ __launch_bounds__(128)
void gemm_mma(const float* __restrict__ A, const float* __restrict__ Bt,
              const float* __restrict__ bias, float* __restrict__ Cout,
              int M, int N, int K)
{
    extern __shared__ float sm[];
    float* As = sm;                  // [3][GSTG]
    float* Bs = sm + 3 * GSTG;       // [3][GSTG]

    const int tid = threadIdx.x;
    const int wid = tid >> 5;            // 0..3
    const int lid = tid & 31;
    const int g   = lid >> 2;
    const int tg  = lid & 3;
    const int wm  = (wid >> 1) * 64;
    const int wn  = (wid & 1) * 64;

    const int m0 = blockIdx.y * 128;
    const int n0 = blockIdx.x * 128;
    const int KT = K >> 4;

    float acc[4][8][4];
#pragma unroll
    for (int i = 0; i < 4; i++)
#pragma unroll
        for (int j = 0; j < 8; j++)
#pragma unroll
            for (int r = 0; r < 4; r++) acc[i][j][r] = 0.0f;

    auto load_stage = [&](int kt, int stg) {
        const float* ga = A  + (size_t)m0 * K + kt * 16;
        const float* gb = Bt + (size_t)n0 * K + kt * 16;
        const uint32_t sa = smem_u32(As + stg * GSTG);
        const uint32_t sb = smem_u32(Bs + stg * GSTG);
#pragma unroll
        for (int i = 0; i < 4; i++) {
            const int c = tid + i * 128;          // 0..511
            const int row = c >> 2;               // 0..127
            const int c16 = c & 3;                // 16B chunk in row
            cp_async16(sa + (row * PAD + c16 * 4) * 4, ga + (size_t)row * K + c16 * 4);
            cp_async16(sb + (row * PAD + c16 * 4) * 4, gb + (size_t)row * K + c16 * 4);
        }
        cp_async_commit();
    };

    load_stage(0, 0);
    load_stage(1, 1);

    int cur = 0;                     // stage holding tile kt
    for (int kt = 0; kt < KT; kt++) {
        cp_async_wait1();            // tile kt resident (this thread)
        __syncthreads();             // visible to all; prev compute finished
        const int nxt = (cur + 2 >= 3) ? cur - 1 : cur + 2;
        if (kt + 2 < KT) load_stage(kt + 2, nxt);

        const float* Ab = As + cur * GSTG;
        const float* Bb = Bs + cur * GSTG;
#pragma unroll
        for (int ks = 0; ks < 2; ks++) {
            uint32_t af[4][4], bf[8][2];
#pragma unroll
            for (int i = 0; i < 4; i++) {
                const uint32_t* p = (const uint32_t*)
                    &Ab[(wm + i * 16 + g) * PAD + ks * 8 + tg];
                af[i][0] = p[0];
                af[i][1] = p[8 * PAD];
                af[i][2] = p[4];
                af[i][3] = p[8 * PAD + 4];
            }
#pragma unroll
            for (int j = 0; j < 8; j++) {
                const uint32_t* p = (const uint32_t*)
                    &Bb[(wn + j * 8 + g) * PAD + ks * 8 + tg];
                bf[j][0] = p[0];
                bf[j][1] = p[4];
            }
#pragma unroll
            for (int i = 0; i < 4; i++)
#pragma unroll
                for (int j = 0; j < 8; j++)
                    mma_tf32(acc[i][j], af[i], bf[j]);
        }
        cur = (cur + 1 >= 3) ? 0 : cur + 1;
    }

    // epilogue
#pragma unroll
    for (int i = 0; i < 4; i++) {
        const int r0 = m0 + wm + i * 16 + g;
        const int r1 = r0 + 8;
#pragma unroll
        for (int j = 0; j < 8; j++) {
            const int c = n0 + wn + j * 8 + 2 * tg;
            const float2 bv = *(const float2*)(bias + c);
            float2 v0, v1;
            v0.x = acc[i][j][0] + bv.x;  v0.y = acc[i][j][1] + bv.y;
            v1.x = acc[i][j][2] + bv.x;  v1.y = acc[i][j][3] + bv.y;
            if (MODE == 0) {
                *(float2*)(Cout + (size_t)r0 * N + c) = v0;
                *(float2*)(Cout + (size_t)r1 * N + c) = v1;
            } else {
                v0.x = tf32r(v0.x); v0.y = tf32r(v0.y);
                v1.x = tf32r(v1.x); v1.y = tf32r(v1.y);
                const int sidx = c >> 10;
                const int rem  = c & (Cc - 1);
                const int h    = rem >> 6;
                const int dd   = rem & (Dc - 1);
                const int b0i = r0 >> 11, t0i = r0 & (Tc - 1);
                const int b1i = r1 >> 11, t1i = r1 & (Tc - 1);
                const size_t base = (size_t)(sidx * Bc) * Hc;
                const size_t d0 = (((base + (size_t)b0i * Hc + h) * Tc + t0i) << 6) + dd;
                const size_t d1 = (((base + (size_t)b1i * Hc + h) * Tc + t1i) << 6) + dd;
                *(float2*)&g_qkv[d0] = v0;
                *(float2*)&g_qkv[d1] = v1;
            }
        }
    }
}

// ---------------------------------------------------------------------------
// Tensor-core causal flash attention (tf32 mma.sync) with phase-split
// cp.async prefetch: K_{i+1} loads overlap softmax+PV_i; V_{i+1} loads
// overlap S_{i+1}. Smem unchanged (53KB) -> 4 CTAs/SM preserved.
// CTA: 64 queries of one (b,h); 4 warps x 16 rows. Key blocks of 64.
// ---------------------------------------------------------------------------
#define KS_ST 68
#define VS_ST 72
#define PS_ST 68
#define ATT_SMEM ((64 * KS_ST + 64 * VS_ST + 4 * 16 * PS_ST) * 4)   // 53248 B

__global__ __launch_bounds__(128)
void attn_mma_kernel(const float* __restrict__ Q, const float* __restrict__ K,
                     const float* __restrict__ V, float* __restrict__ O)
{
    extern __shared__ float sm[];
    float* Ks = sm;                       // [64][68]
    float* Vs = sm + 64 * KS_ST;          // [64][72]
    float* Ps = Vs + 64 * VS_ST;          // [4][16][68]

    const int tid = threadIdx.x;
    const int wid = tid >> 5;
    const int lid = tid & 31;
    const int g   = lid >> 2;
    const int tg  = lid & 3;
    const int bh  = blockIdx.y;
    const int b   = bh >> 4;
    const int h   = bh & 15;
    const int qb  = gridDim.x - 1 - blockIdx.x;   // heavy blocks first
    const int q0  = qb * 64;

    const float SCALE = 0.125f * 1.44269504088896340736f;

    const float* qbase = Q + ((size_t)bh * Tc + q0 + wid * 16) * Dc;
    uint32_t qf[8][4];
#pragma unroll
    for (int k = 0; k < 8; k++) {
        qf[k][0] = __float_as_uint(tf32r(qbase[(size_t)g * Dc       + 8 * k + tg]     * SCALE));
        qf[k][1] = __float_as_uint(tf32r(qbase[(size_t)(g + 8) * Dc + 8 * k + tg]     * SCALE));
        qf[k][2] = __float_as_uint(tf32r(qbase[(size_t)g * Dc       + 8 * k + tg + 4] * SCALE));
        qf[k][3] = __float_as_uint(tf32r(qbase[(size_t)(g + 8) * Dc + 8 * k + tg + 4] * SCALE));
    }

    float o[8][4];
#pragma unroll
    for (int nt = 0; nt < 8; nt++)
#pragma unroll
        for (int r = 0; r < 4; r++) o[nt][r] = 0.0f;
    float m0 = neg_inf(), m1 = neg_inf(), l0 = 0.0f, l1 = 0.0f;

    const float* kg = K + (size_t)bh * Tc * Dc;
    const float* vg = V + (size_t)bh * Tc * Dc;
    const uint32_t ksu = smem_u32(Ks);
    const uint32_t vsu = smem_u32(Vs);
    float* Pw = Ps + wid * 16 * PS_ST;

    // loaders: one operand tile = 1024 16B chunks, 8 per thread
    auto load_k = [&](int t0) {
#pragma unroll
        for (int i = 0; i < 8; i++) {
            const int c = tid + i * 128;
            const int row = c >> 4;
            const int c16 = c & 15;
            cp_async16(ksu + (row * KS_ST + c16 * 4) * 4,
                       kg + (size_t)(t0 + row) * Dc + c16 * 4);
        }
        cp_async_commit();
    };
    auto load_v = [&](int t0) {
#pragma unroll
        for (int i = 0; i < 8; i++) {
            const int c = tid + i * 128;
            const int row = c >> 4;
            const int c16 = c & 15;
            cp_async16(vsu + (row * VS_ST + c16 * 4) * 4,
                       vg + (size_t)(t0 + row) * Dc + c16 * 4);
        }
        cp_async_commit();
    };

    const int NT = qb + 1;
    load_k(0);
    load_v(0);

    for (int it = 0; it < NT; it++) {
        const int t0 = it * 64;

        cp_async_wait1();            // K_it resident
        __syncthreads();

        // S = Q K^T   (16 x 64 per warp)
        float s[8][4];
#pragma unroll
        for (int nt = 0; nt < 8; nt++) {
            s[nt][0] = s[nt][1] = s[nt][2] = s[nt][3] = 0.0f;
#pragma unroll
            for (int k = 0; k < 8; k++) {
                uint32_t bf[2];
                const uint32_t* p = (const uint32_t*)&Ks[(nt * 8 + g) * KS_ST + 8 * k + tg];
                bf[0] = p[0];
                bf[1] = p[4];
                mma_tf32(s[nt], qf[k], bf);
            }
        }

        __syncthreads();             // all warps done reading Ks
        if (it + 1 < NT) load_k(t0 + 64);   // overlaps softmax + PV below

        if (t0 == q0) {              // causal mask on diagonal block
            const int r0 = wid * 16 + g;
            const int r1 = r0 + 8;
#pragma unroll
            for (int nt = 0; nt < 8; nt++) {
                const int c0i = nt * 8 + 2 * tg;
                if (c0i     > r0) s[nt][0] = neg_inf();
                if (c0i + 1 > r0) s[nt][1] = neg_inf();
                if (c0i     > r1) s[nt][2] = neg_inf();
                if (c0i + 1 > r1) s[nt][3] = neg_inf();
            }
        }

        float mt0 = m0, mt1 = m1;
#pragma unroll
        for (int nt = 0; nt < 8; nt++) {
            mt0 = fmaxf(mt0, fmaxf(s[nt][0], s[nt][1]));
            mt1 = fmaxf(mt1, fmaxf(s[nt][2], s[nt][3]));
        }
        mt0 = fmaxf(mt0, __shfl_xor_sync(0xffffffffu, mt0, 1));
        mt0 = fmaxf(mt0, __shfl_xor_sync(0xffffffffu, mt0, 2));
        mt1 = fmaxf(mt1, __shfl_xor_sync(0xffffffffu, mt1, 1));
        mt1 = fmaxf(mt1, __shfl_xor_sync(0xffffffffu, mt1, 2));

        const float a0 = exp2f(m0 - mt0);
        const float a1 = exp2f(m1 - mt1);
        m0 = mt0; m1 = mt1;
        l0 *= a0;  l1 *= a1;
#pragma unroll
        for (int nt = 0; nt < 8; nt++) {
            o[nt][0] *= a0; o[nt][1] *= a0;
            o[nt][2] *= a1; o[nt][3] *= a1;
        }

#pragma unroll
        for (int nt = 0; nt < 8; nt++) {
            float p00 = exp2f(s[nt][0] - mt0);
            float p01 = exp2f(s[nt][1] - mt0);
            float p10 = exp2f(s[nt][2] - mt1);
            float p11 = exp2f(s[nt][3] - mt1);
            p00 = tf32r(p00); p01 = tf32r(p01);
            p10 = tf32r(p10); p11 = tf32r(p11);
            l0 += p00 + p01;
            l1 += p10 + p11;
            *(float2*)&Pw[g * PS_ST + nt * 8 + 2 * tg]       = make_float2(p00, p01);
            *(float2*)&Pw[(g + 8) * PS_ST + nt * 8 + 2 * tg] = make_float2(p10, p11);
        }
        __syncwarp();

        cp_async_wait1();            // V_it resident (K_{it+1} may be in flight)
        __syncthreads();

        // O += P V
#pragma unroll
        for (int k = 0; k < 8; k++) {
            uint32_t af[4];
            af[0] = *(const uint32_t*)&Pw[g * PS_ST       + 8 * k + tg];
            af[1] = *(const uint32_t*)&Pw[(g + 8) * PS_ST + 8 * k + tg];
            af[2] = *(const uint32_t*)&Pw[g * PS_ST       + 8 * k + tg + 4];
            af[3] = *(const uint32_t*)&Pw[(g + 8) * PS_ST + 8 * k + tg + 4];
#pragma unroll
            for (int nt = 0; nt < 8; nt++) {
                uint32_t bf[2];
                bf[0] = *(const uint32_t*)&Vs[(8 * k + tg) * VS_ST     + nt * 8 + g];
                bf[1] = *(const uint32_t*)&Vs[(8 * k + tg + 4) * VS_ST + nt * 8 + g];
                mma_tf32(o[nt], af, bf);
            }
        }

        __syncthreads();             // all warps done reading Vs
        if (it + 1 < NT) load_v(t0 + 64);   // overlaps next S
    }

    l0 += __shfl_xor_sync(0xffffffffu, l0, 1);
    l0 += __shfl_xor_sync(0xffffffffu, l0, 2);
    l1 += __shfl_xor_sync(0xffffffffu, l1, 1);
    l1 += __shfl_xor_sync(0xffffffffu, l1, 2);
    const float inv0 = 1.0f / l0;
    const float inv1 = 1.0f / l1;

    const int row0 = q0 + wid * 16 + g;
    const int row1 = row0 + 8;
    float* ob0 = O + ((size_t)b * Tc + row0) * Cc + h * Dc;
    float* ob1 = O + ((size_t)b * Tc + row1) * Cc + h * Dc;
#pragma unroll
    for (int nt = 0; nt < 8; nt++) {
        const int c = nt * 8 + 2 * tg;
        *(float2*)(ob0 + c) = make_float2(tf32r(o[nt][0] * inv0), tf32r(o[nt][1] * inv0));
        *(float2*)(ob1 + c) = make_float2(tf32r(o[nt][2] * inv1), tf32r(o[nt][3] * inv1));
    }
}

// ---------------------------------------------------------------------------
// Host launcher
// ---------------------------------------------------------------------------
extern "C" void kernel_launch(void* const* d_in, const int* in_sizes, int n_in,
                              void* d_out, int out_size)
{
    const float* x    = (const float*)d_in[0];
    // d_in[1] = mask (static causal — unused)
    const float* Wqkv = (const float*)d_in[2];
    const float* bqkv = (const float*)d_in[3];
    const float* Wout = (const float*)d_in[4];
    const float* bout = (const float*)d_in[5];
    float* out = (float*)d_out;

    float* qkv = nullptr;
    float* att = nullptr;
    float* xr = nullptr;
    float* wqkvT = nullptr;
    float* woutT = nullptr;
    cudaGetSymbolAddress((void**)&qkv, g_qkv);
    cudaGetSymbolAddress((void**)&att, g_att);
    cudaGetSymbolAddress((void**)&xr, g_xr);
    cudaGetSymbolAddress((void**)&wqkvT, g_wqkvT);
    cudaGetSymbolAddress((void**)&woutT, g_woutT);

    static bool attr_set = false;
    if (!attr_set) {
        cudaFuncSetAttribute(attn_mma_kernel,
                             cudaFuncAttributeMaxDynamicSharedMemorySize, ATT_SMEM);
        cudaFuncSetAttribute(gemm_mma<0>,
                             cudaFuncAttributeMaxDynamicSharedMemorySize, GEMM_SMEM);
        cudaFuncSetAttribute(gemm_mma<1>,
                             cudaFuncAttributeMaxDynamicSharedMemorySize, GEMM_SMEM);
        attr_set = true;
    }

    const int M = Bc * Tc;       // 8192

    // 0) prep: round x; transpose+round weights -> K-major [N, K]
    {
        const int nx = M * Cc;
        round_kernel<<<nx / (256 * 4), 256>>>(x, xr, nx);
        dim3 g1(3 * Cc / 32, Cc / 32);
        transpose_kernel<<<g1, 256>>>(Wqkv, wqkvT, Cc, 3 * Cc);
        dim3 g2(Cc / 32, Cc / 32);
        transpose_kernel<<<g2, 256>>>(Wout, woutT, Cc, Cc);
    }

    // 1) QKV GEMM + bias (tf32 mma.sync) -> g_qkv [s][B][H][T][D], rounded
    {
        dim3 grid((3 * Cc) / 128, M / 128);   // (24, 64)
        gemm_mma<1><<<grid, 128, GEMM_SMEM>>>(xr, wqkvT, bqkv, nullptr, M, 3 * Cc, Cc);
    }

    // 2) causal flash attention (tf32 mma.sync) -> g_att [B,T,C], rounded
    {
        const float* Qp = qkv;
        const float* Kp = qkv + BHTD;
        const float* Vp = qkv + 2 * BHTD;
        dim3 grid(Tc / 64, Bc * Hc);          // (32, 64)
        attn_mma_kernel<<<grid, 128, ATT_SMEM>>>(Qp, Kp, Vp, att);
    }

    // 3) output projection + bias (tf32 mma.sync) -> d_out
    {
        dim3 grid(Cc / 128, M / 128);         // (8, 64)
        gemm_mma<0><<<grid, 128, GEMM_SMEM>>>(att, woutT, bout, out, M, Cc, Cc);
    }
}

// round 11
// speedup vs baseline: 4.2711x; 1.0232x over previous
#include <cuda_runtime.h>
#include <cstdint>

// Problem constants
#define Bc 4
#define Tc 2048
#define Cc 1024
#define Hc 16
#define Dc 64
#define BHTD ((size_t)Bc * Hc * Tc * Dc)   // 8388608

// Scratch (static device globals — no allocation allowed)
__device__ float g_qkv[3 * Bc * Hc * Tc * Dc];        // [s][B][H][T][D] tf32-rounded
__device__ float g_att[(size_t)Bc * Tc * Cc];          // [B,T,C] (tf32-rounded)
__device__ float g_xr[(size_t)Bc * Tc * Cc];           // x, tf32-rounded
__device__ float g_wqkvT[3 * Cc * Cc];                 // Wqkv^T [3072,1024], tf32-rounded
__device__ float g_woutT[(size_t)Cc * Cc];             // Wout^T [1024,1024], tf32-rounded

__device__ __forceinline__ float neg_inf() { return __int_as_float(0xff800000); }

__device__ __forceinline__ float tf32r(float x) {
    float y;
    asm("cvt.rna.tf32.f32 %0, %1;" : "=f"(y) : "f"(x));
    return y;
}

__device__ __forceinline__ uint32_t smem_u32(const void* p) {
    uint32_t a;
    asm("{ .reg .u64 t; cvta.to.shared.u64 t, %1; cvt.u32.u64 %0, t; }"
        : "=r"(a) : "l"(p));
    return a;
}

__device__ __forceinline__ void cp_async16(uint32_t smem_dst, const void* gsrc) {
    asm volatile("cp.async.cg.shared.global [%0], [%1], 16;"
                 :: "r"(smem_dst), "l"(gsrc) : "memory");
}
__device__ __forceinline__ void cp_async_commit() {
    asm volatile("cp.async.commit_group;" ::: "memory");
}
__device__ __forceinline__ void cp_async_wait1() {
    asm volatile("cp.async.wait_group 1;" ::: "memory");
}
__device__ __forceinline__ void cp_async_wait0() {
    asm volatile("cp.async.wait_group 0;" ::: "memory");
}

// mma.sync m16n8k8 tf32 (A row-major, B col-major, fp32 accum)
__device__ __forceinline__ void mma_tf32(float* d, const uint32_t* a, const uint32_t* b) {
    asm volatile(
        "mma.sync.aligned.m16n8k8.row.col.f32.tf32.tf32.f32 "
        "{%0,%1,%2,%3}, {%4,%5,%6,%7}, {%8,%9}, {%0,%1,%2,%3};"
        : "+f"(d[0]), "+f"(d[1]), "+f"(d[2]), "+f"(d[3])
        : "r"(a[0]), "r"(a[1]), "r"(a[2]), "r"(a[3]), "r"(b[0]), "r"(b[1]));
}

// ldmatrix x4: four 8-row x 16-byte matrices (== four 8x4 tf32 tiles)
__device__ __forceinline__ void ldsm4(uint32_t* r, uint32_t addr) {
    asm volatile("ldmatrix.sync.aligned.m8n8.x4.shared.b16 {%0,%1,%2,%3}, [%4];"
        : "=r"(r[0]), "=r"(r[1]), "=r"(r[2]), "=r"(r[3]) : "r"(addr));
}

// ---------------------------------------------------------------------------
// Elementwise tf32 rounding
// ---------------------------------------------------------------------------
__global__ __launch_bounds__(256)
void round_kernel(const float* __restrict__ in, float* __restrict__ out, int n)
{
    const int i = (blockIdx.x * 256 + threadIdx.x) * 4;
    if (i < n) {
        float4 v = *(const float4*)(in + i);
        v.x = tf32r(v.x); v.y = tf32r(v.y); v.z = tf32r(v.z); v.w = tf32r(v.w);
        *(float4*)(out + i) = v;
    }
}

// ---------------------------------------------------------------------------
// Transpose + tf32 round: out[c][r] = rna_tf32(in[r][c])  (R rows, C cols)
// ---------------------------------------------------------------------------
__global__ __launch_bounds__(256)
void transpose_kernel(const float* __restrict__ in, float* __restrict__ out,
                      int R, int C)
{
    __shared__ float tile[32][33];
    const int c0 = blockIdx.x * 32;
    const int r0 = blockIdx.y * 32;
    const int x = threadIdx.x & 31;
    const int y = threadIdx.x >> 5;
#pragma unroll
    for (int i = 0; i < 32; i += 8)
        tile[y + i][x] = in[(size_t)(r0 + y + i) * C + c0 + x];
    __syncthreads();
#pragma unroll
    for (int i = 0; i < 32; i += 8)
        out[(size_t)(c0 + y + i) * R + r0 + x] = tf32r(tile[x][y + i]);
}

// ---------------------------------------------------------------------------
// tf32 mma.sync GEMM:  C[M,N] = A[M,K] @ Bt[N,K]^T + bias
// CTA 128x128, 4 warps (2m x 2n), warp tile 64x64, BK=32, 3 stages,
// ldmatrix.x4 fragment loads, warp-staggered ks order.
// MODE 0: plain write.  MODE 1: scatter into g_qkv (tf32-rounded).
// ---------------------------------------------------------------------------
#define PAD32 36                                 // 32 data + 4 pad floats
#define GSTG32 (128 * PAD32)                     // floats per operand per stage
#define GEMM_SMEM (2 * 3 * GSTG32 * 4)           // 110592 bytes

template <int MODE>
__global__ __launch_bounds__(128)
void gemm_mma(const float* __restrict__ A, const float* __restrict__ Bt,
              const float* __restrict__ bias, float* __restrict__ Cout,
              int M, int N, int K)
{
    extern __shared__ float sm[];
    float* As = sm;                  // [3][GSTG32]
    float* Bs = sm + 3 * GSTG32;     // [3][GSTG32]

    const int tid = threadIdx.x;
    const int wid = tid >> 5;            // 0..3
    const int lid = tid & 31;
    const int g   = lid >> 2;
    const int tg  = lid & 3;
    const int wm  = (wid >> 1) * 64;
    const int wn  = (wid & 1) * 64;

    const int m0 = blockIdx.y * 128;
    const int n0 = blockIdx.x * 128;
    const int KT = K >> 5;               // BK=32 tiles

    // ldmatrix per-lane row/col (in floats) within a ks-block
    const int a_r = ((lid >> 3) & 1) * 8 + (lid & 7);
    const int a_c = (lid >> 4) * 4;
    const int b_r = (lid >> 4) * 8 + (lid & 7);
    const int b_c = ((lid >> 3) & 1) * 4;

    float acc[4][8][4];
#pragma unroll
    for (int i = 0; i < 4; i++)
#pragma unroll
        for (int j = 0; j < 8; j++)
#pragma unroll
            for (int r = 0; r < 4; r++) acc[i][j][r] = 0.0f;

    auto load_stage = [&](int kt, int stg) {
        const float* ga = A  + (size_t)m0 * K + kt * 32;
        const float* gb = Bt + (size_t)n0 * K + kt * 32;
        const uint32_t sa = smem_u32(As + stg * GSTG32);
        const uint32_t sb = smem_u32(Bs + stg * GSTG32);
#pragma unroll
        for (int i = 0; i < 8; i++) {
            const int c = tid + i * 128;          // 0..1023
            const int row = c >> 3;               // 0..127
            const int c16 = c & 7;                // 16B chunk in row
            cp_async16(sa + (row * PAD32 + c16 * 4) * 4, ga + (size_t)row * K + c16 * 4);
            cp_async16(sb + (row * PAD32 + c16 * 4) * 4, gb + (size_t)row * K + c16 * 4);
        }
        cp_async_commit();
    };

    load_stage(0, 0);
    load_stage(1, 1);

    int cur = 0;
    for (int kt = 0; kt < KT; kt++) {
        if (kt + 1 < KT) cp_async_wait1();   // tile kt resident
        else             cp_async_wait0();   // last tile: everything done
        __syncthreads();
        const int nxt = (cur + 2 >= 3) ? cur - 1 : cur + 2;
        if (kt + 2 < KT) load_stage(kt + 2, nxt);

        const uint32_t au = smem_u32(As + cur * GSTG32) + 4u * ((wm + a_r) * PAD32 + a_c);
        const uint32_t bu = smem_u32(Bs + cur * GSTG32) + 4u * ((wn + b_r) * PAD32 + b_c);

#pragma unroll
        for (int p = 0; p < 4; p++) {
            const int ks = (p + wid) & 3;    // warp-staggered phase
            uint32_t af[4][4], bf[8][2];
#pragma unroll
            for (int i = 0; i < 4; i++)
                ldsm4(af[i], au + 4u * (i * 16 * PAD32 + ks * 8));
#pragma unroll
            for (int jp = 0; jp < 4; jp++) {
                uint32_t r[4];
                ldsm4(r, bu + 4u * (jp * 16 * PAD32 + ks * 8));
                bf[2 * jp][0]     = r[0];
                bf[2 * jp][1]     = r[1];
                bf[2 * jp + 1][0] = r[2];
                bf[2 * jp + 1][1] = r[3];
            }
#pragma unroll
            for (int i = 0; i < 4; i++)
#pragma unroll
                for (int j = 0; j < 8; j++)
                    mma_tf32(acc[i][j], af[i], bf[j]);
        }
        cur = (cur + 1 >= 3) ? 0 : cur + 1;
    }

    // epilogue
#pragma unroll
    for (int i = 0; i < 4; i++) {
        const int r0 = m0 + wm + i * 16 + g;
        const int r1 = r0 + 8;
#pragma unroll
        for (int j = 0; j < 8; j++) {
            const int c = n0 + wn + j * 8 + 2 * tg;
            const float2 bv = *(const float2*)(bias + c);
            float2 v0, v1;
            v0.x = acc[i][j][0] + bv.x;  v0.y = acc[i][j][1] + bv.y;
            v1.x = acc[i][j][2] + bv.x;  v1.y = acc[i][j][3] + bv.y;
            if (MODE == 0) {
                *(float2*)(Cout + (size_t)r0 * N + c) = v0;
                *(float2*)(Cout + (size_t)r1 * N + c) = v1;
            } else {
                v0.x = tf32r(v0.x); v0.y = tf32r(v0.y);
                v1.x = tf32r(v1.x); v1.y = tf32r(v1.y);
                const int sidx = c >> 10;
                const int rem  = c & (Cc - 1);
                const int h    = rem >> 6;
                const int dd   = rem & (Dc - 1);
                const int b0i = r0 >> 11, t0i = r0 & (Tc - 1);
                const int b1i = r1 >> 11, t1i = r1 & (Tc - 1);
                const size_t base = (size_t)(sidx * Bc) * Hc;
                const size_t d0 = (((base + (size_t)b0i * Hc + h) * Tc + t0i) << 6) + dd;
                const size_t d1 = (((base + (size_t)b1i * Hc + h) * Tc + t1i) << 6) + dd;
                *(float2*)&g_qkv[d0] = v0;
                *(float2*)&g_qkv[d1] = v1;
            }
        }
    }
}

// ---------------------------------------------------------------------------
// Tensor-core causal flash attention (tf32 mma.sync) with phase-split
// cp.async prefetch (round-10 structure; final-V wait race fixed).
// ---------------------------------------------------------------------------
#define KS_ST 68
#define VS_ST 72
#define PS_ST 68
#define ATT_SMEM ((64 * KS_ST + 64 * VS_ST + 4 * 16 * PS_ST) * 4)   // 53248 B

__global__ __launch_bounds__(128)
void attn_mma_kernel(const float* __restrict__ Q, const float* __restrict__ K,
                     const float* __restrict__ V, float* __restrict__ O)
{
    extern __shared__ float sm[];
    float* Ks = sm;                       // [64][68]
    float* Vs = sm + 64 * KS_ST;          // [64][72]
    float* Ps = Vs + 64 * VS_ST;          // [4][16][68]

    const int tid = threadIdx.x;
    const int wid = tid >> 5;
    const int lid = tid & 31;
    const int g   = lid >> 2;
    const int tg  = lid & 3;
    const int bh  = blockIdx.y;
    const int b   = bh >> 4;
    const int h   = bh & 15;
    const int qb  = gridDim.x - 1 - blockIdx.x;   // heavy blocks first
    const int q0  = qb * 64;

    const float SCALE = 0.125f * 1.44269504088896340736f;

    const float* qbase = Q + ((size_t)bh * Tc + q0 + wid * 16) * Dc;
    uint32_t qf[8][4];
#pragma unroll
    for (int k = 0; k < 8; k++) {
        qf[k][0] = __float_as_uint(tf32r(qbase[(size_t)g * Dc       + 8 * k + tg]     * SCALE));
        qf[k][1] = __float_as_uint(tf32r(qbase[(size_t)(g + 8) * Dc + 8 * k + tg]     * SCALE));
        qf[k][2] = __float_as_uint(tf32r(qbase[(size_t)g * Dc       + 8 * k + tg + 4] * SCALE));
        qf[k][3] = __float_as_uint(tf32r(qbase[(size_t)(g + 8) * Dc + 8 * k + tg + 4] * SCALE));
    }

    float o[8][4];
#pragma unroll
    for (int nt = 0; nt < 8; nt++)
#pragma unroll
        for (int r = 0; r < 4; r++) o[nt][r] = 0.0f;
    float m0 = neg_inf(), m1 = neg_inf(), l0 = 0.0f, l1 = 0.0f;

    const float* kg = K + (size_t)bh * Tc * Dc;
    const float* vg = V + (size_t)bh * Tc * Dc;
    const uint32_t ksu = smem_u32(Ks);
    const uint32_t vsu = smem_u32(Vs);
    float* Pw = Ps + wid * 16 * PS_ST;

    auto load_k = [&](int t0) {
#pragma unroll
        for (int i = 0; i < 8; i++) {
            const int c = tid + i * 128;
            const int row = c >> 4;
            const int c16 = c & 15;
            cp_async16(ksu + (row * KS_ST + c16 * 4) * 4,
                       kg + (size_t)(t0 + row) * Dc + c16 * 4);
        }
        cp_async_commit();
    };
    auto load_v = [&](int t0) {
#pragma unroll
        for (int i = 0; i < 8; i++) {
            const int c = tid + i * 128;
            const int row = c >> 4;
            const int c16 = c & 15;
            cp_async16(vsu + (row * VS_ST + c16 * 4) * 4,
                       vg + (size_t)(t0 + row) * Dc + c16 * 4);
        }
        cp_async_commit();
    };

    const int NT = qb + 1;
    load_k(0);
    load_v(0);

    for (int it = 0; it < NT; it++) {
        const int t0 = it * 64;

        cp_async_wait1();            // K_it resident (V_it is the newer group)
        __syncthreads();

        // S = Q K^T   (16 x 64 per warp)
        float s[8][4];
#pragma unroll
        for (int nt = 0; nt < 8; nt++) {
            s[nt][0] = s[nt][1] = s[nt][2] = s[nt][3] = 0.0f;
#pragma unroll
            for (int k = 0; k < 8; k++) {
                uint32_t bf[2];
                const uint32_t* p = (const uint32_t*)&Ks[(nt * 8 + g) * KS_ST + 8 * k + tg];
                bf[0] = p[0];
                bf[1] = p[4];
                mma_tf32(s[nt], qf[k], bf);
            }
        }

        __syncthreads();             // all warps done reading Ks
        if (it + 1 < NT) load_k(t0 + 64);   // overlaps softmax + PV below

        if (t0 == q0) {              // causal mask on diagonal block
            const int r0 = wid * 16 + g;
            const int r1 = r0 + 8;
#pragma unroll
            for (int nt = 0; nt < 8; nt++) {
                const int c0i = nt * 8 + 2 * tg;
                if (c0i     > r0) s[nt][0] = neg_inf();
                if (c0i + 1 > r0) s[nt][1] = neg_inf();
                if (c0i     > r1) s[nt][2] = neg_inf();
                if (c0i + 1 > r1) s[nt][3] = neg_inf();
            }
        }

        float mt0 = m0, mt1 = m1;
#pragma unroll
        for (int nt = 0; nt < 8; nt++) {
            mt0 = fmaxf(mt0, fmaxf(s[nt][0], s[nt][1]));
            mt1 = fmaxf(mt1, fmaxf(s[nt][2], s[nt][3]));
        }
        mt0 = fmaxf(mt0, __shfl_xor_sync(0xffffffffu, mt0, 1));
        mt0 = fmaxf(mt0, __shfl_xor_sync(0xffffffffu, mt0, 2));
        mt1 = fmaxf(mt1, __shfl_xor_sync(0xffffffffu, mt1, 1));
        mt1 = fmaxf(mt1, __shfl_xor_sync(0xffffffffu, mt1, 2));

        const float a0 = exp2f(m0 - mt0);
        const float a1 = exp2f(m1 - mt1);
        m0 = mt0; m1 = mt1;
        l0 *= a0;  l1 *= a1;
#pragma unroll
        for (int nt = 0; nt < 8; nt++) {
            o[nt][0] *= a0; o[nt][1] *= a0;
            o[nt][2] *= a1; o[nt][3] *= a1;
        }

#pragma unroll
        for (int nt = 0; nt < 8; nt++) {
            float p00 = exp2f(s[nt][0] - mt0);
            float p01 = exp2f(s[nt][1] - mt0);
            float p10 = exp2f(s[nt][2] - mt1);
            float p11 = exp2f(s[nt][3] - mt1);
            p00 = tf32r(p00); p01 = tf32r(p01);
            p10 = tf32r(p10); p11 = tf32r(p11);
            l0 += p00 + p01;
            l1 += p10 + p11;
            *(float2*)&Pw[g * PS_ST + nt * 8 + 2 * tg]       = make_float2(p00, p01);
            *(float2*)&Pw[(g + 8) * PS_ST + nt * 8 + 2 * tg] = make_float2(p10, p11);
        }
        __syncwarp();

        if (it + 1 < NT) cp_async_wait1();   // V_it resident (K_{it+1} in flight)
        else             cp_async_wait0();   // final V: guarantee completion
        __syncthreads();

        // O += P V
#pragma unroll
        for (int k = 0; k < 8; k++) {
            uint32_t af[4];
            af[0] = *(const uint32_t*)&Pw[g * PS_ST       + 8 * k + tg];
            af[1] = *(const uint32_t*)&Pw[(g + 8) * PS_ST + 8 * k + tg];
            af[2] = *(const uint32_t*)&Pw[g * PS_ST       + 8 * k + tg + 4];
            af[3] = *(const uint32_t*)&Pw[(g + 8) * PS_ST + 8 * k + tg + 4];
#pragma unroll
            for (int nt = 0; nt < 8; nt++) {
                uint32_t bf[2];
                bf[0] = *(const uint32_t*)&Vs[(8 * k + tg) * VS_ST     + nt * 8 + g];
                bf[1] = *(const uint32_t*)&Vs[(8 * k + tg + 4) * VS_ST + nt * 8 + g];
                mma_tf32(o[nt], af, bf);
            }
        }

        __syncthreads();             // all warps done reading Vs
        if (it + 1 < NT) load_v(t0 + 64);   // overlaps next S
    }

    l0 += __shfl_xor_sync(0xffffffffu, l0, 1);
    l0 += __shfl_xor_sync(0xffffffffu, l0, 2);
    l1 += __shfl_xor_sync(0xffffffffu, l1, 1);
    l1 += __shfl_xor_sync(0xffffffffu, l1, 2);
    const float inv0 = 1.0f / l0;
    const float inv1 = 1.0f / l1;

    const int row0 = q0 + wid * 16 + g;
    const int row1 = row0 + 8;
    float* ob0 = O + ((size_t)b * Tc + row0) * Cc + h * Dc;
    float* ob1 = O + ((size_t)b * Tc + row1) * Cc + h * Dc;
#pragma unroll
    for (int nt = 0; nt < 8; nt++) {
        const int c = nt * 8 + 2 * tg;
        *(float2*)(ob0 + c) = make_float2(tf32r(o[nt][0] * inv0), tf32r(o[nt][1] * inv0));
        *(float2*)(ob1 + c) = make_float2(tf32r(o[nt][2] * inv1), tf32r(o[nt][3] * inv1));
    }
}

// ---------------------------------------------------------------------------
// Host launcher
// ---------------------------------------------------------------------------
extern "C" void kernel_launch(void* const* d_in, const int* in_sizes, int n_in,
                              void* d_out, int out_size)
{
    const float* x    = (const float*)d_in[0];
    // d_in[1] = mask (static causal — unused)
    const float* Wqkv = (const float*)d_in[2];
    const float* bqkv = (const float*)d_in[3];
    const float* Wout = (const float*)d_in[4];
    const float* bout = (const float*)d_in[5];
    float* out = (float*)d_out;

    float* qkv = nullptr;
    float* att = nullptr;
    float* xr = nullptr;
    float* wqkvT = nullptr;
    float* woutT = nullptr;
    cudaGetSymbolAddress((void**)&qkv, g_qkv);
    cudaGetSymbolAddress((void**)&att, g_att);
    cudaGetSymbolAddress((void**)&xr, g_xr);
    cudaGetSymbolAddress((void**)&wqkvT, g_wqkvT);
    cudaGetSymbolAddress((void**)&woutT, g_woutT);

    static bool attr_set = false;
    if (!attr_set) {
        cudaFuncSetAttribute(attn_mma_kernel,
                             cudaFuncAttributeMaxDynamicSharedMemorySize, ATT_SMEM);
        cudaFuncSetAttribute(gemm_mma<0>,
                             cudaFuncAttributeMaxDynamicSharedMemorySize, GEMM_SMEM);
        cudaFuncSetAttribute(gemm_mma<1>,
                             cudaFuncAttributeMaxDynamicSharedMemorySize, GEMM_SMEM);
        attr_set = true;
    }

    const int M = Bc * Tc;       // 8192

    // 0) prep: round x; transpose+round weights -> K-major [N, K]
    {
        const int nx = M * Cc;
        round_kernel<<<nx / (256 * 4), 256>>>(x, xr, nx);
        dim3 g1(3 * Cc / 32, Cc / 32);
        transpose_kernel<<<g1, 256>>>(Wqkv, wqkvT, Cc, 3 * Cc);
        dim3 g2(Cc / 32, Cc / 32);
        transpose_kernel<<<g2, 256>>>(Wout, woutT, Cc, Cc);
    }

    // 1) QKV GEMM + bias (tf32 mma.sync) -> g_qkv [s][B][H][T][D], rounded
    {
        dim3 grid((3 * Cc) / 128, M / 128);   // (24, 64)
        gemm_mma<1><<<grid, 128, GEMM_SMEM>>>(xr, wqkvT, bqkv, nullptr, M, 3 * Cc, Cc);
    }

    // 2) causal flash attention (tf32 mma.sync) -> g_att [B,T,C], rounded
    {
        const float* Qp = qkv;
        const float* Kp = qkv + BHTD;
        const float* Vp = qkv + 2 * BHTD;
        dim3 grid(Tc / 64, Bc * Hc);          // (32, 64)
        attn_mma_kernel<<<grid, 128, ATT_SMEM>>>(Qp, Kp, Vp, att);
    }

    // 3) output projection + bias (tf32 mma.sync) -> d_out
    {
        dim3 grid(Cc / 128, M / 128);         // (8, 64)
        gemm_mma<0><<<grid, 128, GEMM_SMEM>>>(att, woutT, bout, out, M, Cc, Cc);
    }
}

// round 12
// speedup vs baseline: 4.4970x; 1.0529x over previous
#include <cuda_runtime.h>
#include <cstdint>

// Problem constants
#define Bc 4
#define Tc 2048
#define Cc 1024
#define Hc 16
#define Dc 64
#define BHTD ((size_t)Bc * Hc * Tc * Dc)   // 8388608

// Scratch (static device globals — no allocation allowed)
__device__ float g_qkv[3 * Bc * Hc * Tc * Dc];        // [s][B][H][T][D] tf32-rounded
__device__ float g_att[(size_t)Bc * Tc * Cc];          // [B,T,C] (tf32-rounded)
__device__ float g_xr[(size_t)Bc * Tc * Cc];           // x, tf32-rounded
__device__ float g_wqkvT[3 * Cc * Cc];                 // Wqkv^T [3072,1024], tf32-rounded
__device__ float g_woutT[(size_t)Cc * Cc];             // Wout^T [1024,1024], tf32-rounded

__device__ __forceinline__ float neg_inf() { return __int_as_float(0xff800000); }

__device__ __forceinline__ float tf32r(float x) {
    float y;
    asm("cvt.rna.tf32.f32 %0, %1;" : "=f"(y) : "f"(x));
    return y;
}

__device__ __forceinline__ uint32_t smem_u32(const void* p) {
    uint32_t a;
    asm("{ .reg .u64 t; cvta.to.shared.u64 t, %1; cvt.u32.u64 %0, t; }"
        : "=r"(a) : "l"(p));
    return a;
}

__device__ __forceinline__ void cp_async16(uint32_t smem_dst, const void* gsrc) {
    asm volatile("cp.async.cg.shared.global [%0], [%1], 16;"
                 :: "r"(smem_dst), "l"(gsrc) : "memory");
}
__device__ __forceinline__ void cp_async_commit() {
    asm volatile("cp.async.commit_group;" ::: "memory");
}
__device__ __forceinline__ void cp_async_wait1() {
    asm volatile("cp.async.wait_group 1;" ::: "memory");
}
__device__ __forceinline__ void cp_async_wait0() {
    asm volatile("cp.async.wait_group 0;" ::: "memory");
}

// mma.sync m16n8k8 tf32 (A row-major, B col-major, fp32 accum)
__device__ __forceinline__ void mma_tf32(float* d, const uint32_t* a, const uint32_t* b) {
    asm volatile(
        "mma.sync.aligned.m16n8k8.row.col.f32.tf32.tf32.f32 "
        "{%0,%1,%2,%3}, {%4,%5,%6,%7}, {%8,%9}, {%0,%1,%2,%3};"
        : "+f"(d[0]), "+f"(d[1]), "+f"(d[2]), "+f"(d[3])
        : "r"(a[0]), "r"(a[1]), "r"(a[2]), "r"(a[3]), "r"(b[0]), "r"(b[1]));
}

// ldmatrix x4: four 8-row x 16-byte matrices (== four 8x4 tf32 tiles)
__device__ __forceinline__ void ldsm4(uint32_t* r, uint32_t addr) {
    asm volatile("ldmatrix.sync.aligned.m8n8.x4.shared.b16 {%0,%1,%2,%3}, [%4];"
        : "=r"(r[0]), "=r"(r[1]), "=r"(r[2]), "=r"(r[3]) : "r"(addr));
}

// ---------------------------------------------------------------------------
// Elementwise tf32 rounding
// ---------------------------------------------------------------------------
__global__ __launch_bounds__(256)
void round_kernel(const float* __restrict__ in, float* __restrict__ out, int n)
{
    const int i = (blockIdx.x * 256 + threadIdx.x) * 4;
    if (i < n) {
        float4 v = *(const float4*)(in + i);
        v.x = tf32r(v.x); v.y = tf32r(v.y); v.z = tf32r(v.z); v.w = tf32r(v.w);
        *(float4*)(out + i) = v;
    }
}

// ---------------------------------------------------------------------------
// Transpose + tf32 round: out[c][r] = rna_tf32(in[r][c])  (R rows, C cols)
// ---------------------------------------------------------------------------
__global__ __launch_bounds__(256)
void transpose_kernel(const float* __restrict__ in, float* __restrict__ out,
                      int R, int C)
{
    __shared__ float tile[32][33];
    const int c0 = blockIdx.x * 32;
    const int r0 = blockIdx.y * 32;
    const int x = threadIdx.x & 31;
    const int y = threadIdx.x >> 5;
#pragma unroll
    for (int i = 0; i < 32; i += 8)
        tile[y + i][x] = in[(size_t)(r0 + y + i) * C + c0 + x];
    __syncthreads();
#pragma unroll
    for (int i = 0; i < 32; i += 8)
        out[(size_t)(c0 + y + i) * R + r0 + x] = tf32r(tile[x][y + i]);
}

// ---------------------------------------------------------------------------
// tf32 mma.sync GEMM:  C[M,N] = A[M,K] @ Bt[N,K]^T + bias
// CTA 128x128, 256 threads = 8 warps (2m x 4n), warp tile 64x32, BK=32,
// 3-stage cp.async pipeline, ldmatrix.x4 loads, warp-staggered ks order.
// 2 CTAs/SM -> 4 warps/SMSP for latency hiding.
// MODE 0: plain write.  MODE 1: scatter into g_qkv (tf32-rounded).
// ---------------------------------------------------------------------------
#define PAD32 36                                 // 32 data + 4 pad floats
#define GSTG32 (128 * PAD32)                     // floats per operand per stage
#define GEMM_SMEM (2 * 3 * GSTG32 * 4)           // 110592 bytes

template <int MODE>
__global__ __launch_bounds__(256, 2)
void gemm_mma(const float* __restrict__ A, const float* __restrict__ Bt,
              const float* __restrict__ bias, float* __restrict__ Cout,
              int M, int N, int K)
{
    extern __shared__ float sm[];
    float* As = sm;                  // [3][GSTG32]
    float* Bs = sm + 3 * GSTG32;     // [3][GSTG32]

    const int tid = threadIdx.x;
    const int wid = tid >> 5;            // 0..7
    const int lid = tid & 31;
    const int g   = lid >> 2;
    const int tg  = lid & 3;
    const int wm  = (wid >> 2) * 64;     // 2 m-groups
    const int wn  = (wid & 3) * 32;      // 4 n-groups

    const int m0 = blockIdx.y * 128;
    const int n0 = blockIdx.x * 128;
    const int KT = K >> 5;               // BK=32 tiles

    // ldmatrix per-lane row/col (in floats) within a ks-block
    const int a_r = ((lid >> 3) & 1) * 8 + (lid & 7);
    const int a_c = (lid >> 4) * 4;
    const int b_r = (lid >> 4) * 8 + (lid & 7);
    const int b_c = ((lid >> 3) & 1) * 4;

    float acc[4][4][4];
#pragma unroll
    for (int i = 0; i < 4; i++)
#pragma unroll
        for (int j = 0; j < 4; j++)
#pragma unroll
            for (int r = 0; r < 4; r++) acc[i][j][r] = 0.0f;

    auto load_stage = [&](int kt, int stg) {
        const float* ga = A  + (size_t)m0 * K + kt * 32;
        const float* gb = Bt + (size_t)n0 * K + kt * 32;
        const uint32_t sa = smem_u32(As + stg * GSTG32);
        const uint32_t sb = smem_u32(Bs + stg * GSTG32);
#pragma unroll
        for (int i = 0; i < 4; i++) {
            const int c = tid + i * 256;          // 0..1023
            const int row = c >> 3;               // 0..127
            const int c16 = c & 7;                // 16B chunk in row
            cp_async16(sa + (row * PAD32 + c16 * 4) * 4, ga + (size_t)row * K + c16 * 4);
            cp_async16(sb + (row * PAD32 + c16 * 4) * 4, gb + (size_t)row * K + c16 * 4);
        }
        cp_async_commit();
    };

    load_stage(0, 0);
    load_stage(1, 1);

    int cur = 0;
    for (int kt = 0; kt < KT; kt++) {
        if (kt + 1 < KT) cp_async_wait1();   // tile kt resident
        else             cp_async_wait0();   // last tile: everything done
        __syncthreads();
        const int nxt = (cur + 2 >= 3) ? cur - 1 : cur + 2;
        if (kt + 2 < KT) load_stage(kt + 2, nxt);

        const uint32_t au = smem_u32(As + cur * GSTG32) + 4u * ((wm + a_r) * PAD32 + a_c);
        const uint32_t bu = smem_u32(Bs + cur * GSTG32) + 4u * ((wn + b_r) * PAD32 + b_c);

#pragma unroll
        for (int p = 0; p < 4; p++) {
            const int ks = (p + wid) & 3;    // warp-staggered phase
            uint32_t af[4][4], bf[4][2];
#pragma unroll
            for (int i = 0; i < 4; i++)
                ldsm4(af[i], au + 4u * (i * 16 * PAD32 + ks * 8));
#pragma unroll
            for (int jp = 0; jp < 2; jp++) {
                uint32_t r[4];
                ldsm4(r, bu + 4u * (jp * 16 * PAD32 + ks * 8));
                bf[2 * jp][0]     = r[0];
                bf[2 * jp][1]     = r[1];
                bf[2 * jp + 1][0] = r[2];
                bf[2 * jp + 1][1] = r[3];
            }
#pragma unroll
            for (int i = 0; i < 4; i++)
#pragma unroll
                for (int j = 0; j < 4; j++)
                    mma_tf32(acc[i][j], af[i], bf[j]);
        }
        cur = (cur + 1 >= 3) ? 0 : cur + 1;
    }

    // epilogue
#pragma unroll
    for (int i = 0; i < 4; i++) {
        const int r0 = m0 + wm + i * 16 + g;
        const int r1 = r0 + 8;
#pragma unroll
        for (int j = 0; j < 4; j++) {
            const int c = n0 + wn + j * 8 + 2 * tg;
            const float2 bv = *(const float2*)(bias + c);
            float2 v0, v1;
            v0.x = acc[i][j][0] + bv.x;  v0.y = acc[i][j][1] + bv.y;
            v1.x = acc[i][j][2] + bv.x;  v1.y = acc[i][j][3] + bv.y;
            if (MODE == 0) {
                *(float2*)(Cout + (size_t)r0 * N + c) = v0;
                *(float2*)(Cout + (size_t)r1 * N + c) = v1;
            } else {
                v0.x = tf32r(v0.x); v0.y = tf32r(v0.y);
                v1.x = tf32r(v1.x); v1.y = tf32r(v1.y);
                const int sidx = c >> 10;
                const int rem  = c & (Cc - 1);
                const int h    = rem >> 6;
                const int dd   = rem & (Dc - 1);
                const int b0i = r0 >> 11, t0i = r0 & (Tc - 1);
                const int b1i = r1 >> 11, t1i = r1 & (Tc - 1);
                const size_t base = (size_t)(sidx * Bc) * Hc;
                const size_t d0 = (((base + (size_t)b0i * Hc + h) * Tc + t0i) << 6) + dd;
                const size_t d1 = (((base + (size_t)b1i * Hc + h) * Tc + t1i) << 6) + dd;
                *(float2*)&g_qkv[d0] = v0;
                *(float2*)&g_qkv[d1] = v1;
            }
        }
    }
}

// ---------------------------------------------------------------------------
// Tensor-core causal flash attention (tf32 mma.sync) with phase-split
// cp.async prefetch. (unchanged from round 11)
// ---------------------------------------------------------------------------
#define KS_ST 68
#define VS_ST 72
#define PS_ST 68
#define ATT_SMEM ((64 * KS_ST + 64 * VS_ST + 4 * 16 * PS_ST) * 4)   // 53248 B

__global__ __launch_bounds__(128)
void attn_mma_kernel(const float* __restrict__ Q, const float* __restrict__ K,
                     const float* __restrict__ V, float* __restrict__ O)
{
    extern __shared__ float sm[];
    float* Ks = sm;                       // [64][68]
    float* Vs = sm + 64 * KS_ST;          // [64][72]
    float* Ps = Vs + 64 * VS_ST;          // [4][16][68]

    const int tid = threadIdx.x;
    const int wid = tid >> 5;
    const int lid = tid & 31;
    const int g   = lid >> 2;
    const int tg  = lid & 3;
    const int bh  = blockIdx.y;
    const int b   = bh >> 4;
    const int h   = bh & 15;
    const int qb  = gridDim.x - 1 - blockIdx.x;   // heavy blocks first
    const int q0  = qb * 64;

    const float SCALE = 0.125f * 1.44269504088896340736f;

    const float* qbase = Q + ((size_t)bh * Tc + q0 + wid * 16) * Dc;
    uint32_t qf[8][4];
#pragma unroll
    for (int k = 0; k < 8; k++) {
        qf[k][0] = __float_as_uint(tf32r(qbase[(size_t)g * Dc       + 8 * k + tg]     * SCALE));
        qf[k][1] = __float_as_uint(tf32r(qbase[(size_t)(g + 8) * Dc + 8 * k + tg]     * SCALE));
        qf[k][2] = __float_as_uint(tf32r(qbase[(size_t)g * Dc       + 8 * k + tg + 4] * SCALE));
        qf[k][3] = __float_as_uint(tf32r(qbase[(size_t)(g + 8) * Dc + 8 * k + tg + 4] * SCALE));
    }

    float o[8][4];
#pragma unroll
    for (int nt = 0; nt < 8; nt++)
#pragma unroll
        for (int r = 0; r < 4; r++) o[nt][r] = 0.0f;
    float m0 = neg_inf(), m1 = neg_inf(), l0 = 0.0f, l1 = 0.0f;

    const float* kg = K + (size_t)bh * Tc * Dc;
    const float* vg = V + (size_t)bh * Tc * Dc;
    const uint32_t ksu = smem_u32(Ks);
    const uint32_t vsu = smem_u32(Vs);
    float* Pw = Ps + wid * 16 * PS_ST;

    auto load_k = [&](int t0) {
#pragma unroll
        for (int i = 0; i < 8; i++) {
            const int c = tid + i * 128;
            const int row = c >> 4;
            const int c16 = c & 15;
            cp_async16(ksu + (row * KS_ST + c16 * 4) * 4,
                       kg + (size_t)(t0 + row) * Dc + c16 * 4);
        }
        cp_async_commit();
    };
    auto load_v = [&](int t0) {
#pragma unroll
        for (int i = 0; i < 8; i++) {
            const int c = tid + i * 128;
            const int row = c >> 4;
            const int c16 = c & 15;
            cp_async16(vsu + (row * VS_ST + c16 * 4) * 4,
                       vg + (size_t)(t0 + row) * Dc + c16 * 4);
        }
        cp_async_commit();
    };

    const int NT = qb + 1;
    load_k(0);
    load_v(0);

    for (int it = 0; it < NT; it++) {
        const int t0 = it * 64;

        cp_async_wait1();            // K_it resident (V_it is the newer group)
        __syncthreads();

        // S = Q K^T   (16 x 64 per warp)
        float s[8][4];
#pragma unroll
        for (int nt = 0; nt < 8; nt++) {
            s[nt][0] = s[nt][1] = s[nt][2] = s[nt][3] = 0.0f;
#pragma unroll
            for (int k = 0; k < 8; k++) {
                uint32_t bf[2];
                const uint32_t* p = (const uint32_t*)&Ks[(nt * 8 + g) * KS_ST + 8 * k + tg];
                bf[0] = p[0];
                bf[1] = p[4];
                mma_tf32(s[nt], qf[k], bf);
            }
        }

        __syncthreads();             // all warps done reading Ks
        if (it + 1 < NT) load_k(t0 + 64);   // overlaps softmax + PV below

        if (t0 == q0) {              // causal mask on diagonal block
            const int r0 = wid * 16 + g;
            const int r1 = r0 + 8;
#pragma unroll
            for (int nt = 0; nt < 8; nt++) {
                const int c0i = nt * 8 + 2 * tg;
                if (c0i     > r0) s[nt][0] = neg_inf();
                if (c0i + 1 > r0) s[nt][1] = neg_inf();
                if (c0i     > r1) s[nt][2] = neg_inf();
                if (c0i + 1 > r1) s[nt][3] = neg_inf();
            }
        }

        float mt0 = m0, mt1 = m1;
#pragma unroll
        for (int nt = 0; nt < 8; nt++) {
            mt0 = fmaxf(mt0, fmaxf(s[nt][0], s[nt][1]));
            mt1 = fmaxf(mt1, fmaxf(s[nt][2], s[nt][3]));
        }
        mt0 = fmaxf(mt0, __shfl_xor_sync(0xffffffffu, mt0, 1));
        mt0 = fmaxf(mt0, __shfl_xor_sync(0xffffffffu, mt0, 2));
        mt1 = fmaxf(mt1, __shfl_xor_sync(0xffffffffu, mt1, 1));
        mt1 = fmaxf(mt1, __shfl_xor_sync(0xffffffffu, mt1, 2));

        const float a0 = exp2f(m0 - mt0);
        const float a1 = exp2f(m1 - mt1);
        m0 = mt0; m1 = mt1;
        l0 *= a0;  l1 *= a1;
#pragma unroll
        for (int nt = 0; nt < 8; nt++) {
            o[nt][0] *= a0; o[nt][1] *= a0;
            o[nt][2] *= a1; o[nt][3] *= a1;
        }

#pragma unroll
        for (int nt = 0; nt < 8; nt++) {
            float p00 = exp2f(s[nt][0] - mt0);
            float p01 = exp2f(s[nt][1] - mt0);
            float p10 = exp2f(s[nt][2] - mt1);
            float p11 = exp2f(s[nt][3] - mt1);
            p00 = tf32r(p00); p01 = tf32r(p01);
            p10 = tf32r(p10); p11 = tf32r(p11);
            l0 += p00 + p01;
            l1 += p10 + p11;
            *(float2*)&Pw[g * PS_ST + nt * 8 + 2 * tg]       = make_float2(p00, p01);
            *(float2*)&Pw[(g + 8) * PS_ST + nt * 8 + 2 * tg] = make_float2(p10, p11);
        }
        __syncwarp();

        if (it + 1 < NT) cp_async_wait1();   // V_it resident (K_{it+1} in flight)
        else             cp_async_wait0();   // final V: guarantee completion
        __syncthreads();

        // O += P V
#pragma unroll
        for (int k = 0; k < 8; k++) {
            uint32_t af[4];
            af[0] = *(const uint32_t*)&Pw[g * PS_ST       + 8 * k + tg];
            af[1] = *(const uint32_t*)&Pw[(g + 8) * PS_ST + 8 * k + tg];
            af[2] = *(const uint32_t*)&Pw[g * PS_ST       + 8 * k + tg + 4];
            af[3] = *(const uint32_t*)&Pw[(g + 8) * PS_ST + 8 * k + tg + 4];
#pragma unroll
            for (int nt = 0; nt < 8; nt++) {
                uint32_t bf[2];
                bf[0] = *(const uint32_t*)&Vs[(8 * k + tg) * VS_ST     + nt * 8 + g];
                bf[1] = *(const uint32_t*)&Vs[(8 * k + tg + 4) * VS_ST + nt * 8 + g];
                mma_tf32(o[nt], af, bf);
            }
        }

        __syncthreads();             // all warps done reading Vs
        if (it + 1 < NT) load_v(t0 + 64);   // overlaps next S
    }

    l0 += __shfl_xor_sync(0xffffffffu, l0, 1);
    l0 += __shfl_xor_sync(0xffffffffu, l0, 2);
    l1 += __shfl_xor_sync(0xffffffffu, l1, 1);
    l1 += __shfl_xor_sync(0xffffffffu, l1, 2);
    const float inv0 = 1.0f / l0;
    const float inv1 = 1.0f / l1;

    const int row0 = q0 + wid * 16 + g;
    const int row1 = row0 + 8;
    float* ob0 = O + ((size_t)b * Tc + row0) * Cc + h * Dc;
    float* ob1 = O + ((size_t)b * Tc + row1) * Cc + h * Dc;
#pragma unroll
    for (int nt = 0; nt < 8; nt++) {
        const int c = nt * 8 + 2 * tg;
        *(float2*)(ob0 + c) = make_float2(tf32r(o[nt][0] * inv0), tf32r(o[nt][1] * inv0));
        *(float2*)(ob1 + c) = make_float2(tf32r(o[nt][2] * inv1), tf32r(o[nt][3] * inv1));
    }
}

// ---------------------------------------------------------------------------
// Host launcher
// ---------------------------------------------------------------------------
extern "C" void kernel_launch(void* const* d_in, const int* in_sizes, int n_in,
                              void* d_out, int out_size)
{
    const float* x    = (const float*)d_in[0];
    // d_in[1] = mask (static causal — unused)
    const float* Wqkv = (const float*)d_in[2];
    const float* bqkv = (const float*)d_in[3];
    const float* Wout = (const float*)d_in[4];
    const float* bout = (const float*)d_in[5];
    float* out = (float*)d_out;

    float* qkv = nullptr;
    float* att = nullptr;
    float* xr = nullptr;
    float* wqkvT = nullptr;
    float* woutT = nullptr;
    cudaGetSymbolAddress((void**)&qkv, g_qkv);
    cudaGetSymbolAddress((void**)&att, g_att);
    cudaGetSymbolAddress((void**)&xr, g_xr);
    cudaGetSymbolAddress((void**)&wqkvT, g_wqkvT);
    cudaGetSymbolAddress((void**)&woutT, g_woutT);

    static bool attr_set = false;
    if (!attr_set) {
        cudaFuncSetAttribute(attn_mma_kernel,
                             cudaFuncAttributeMaxDynamicSharedMemorySize, ATT_SMEM);
        cudaFuncSetAttribute(gemm_mma<0>,
                             cudaFuncAttributeMaxDynamicSharedMemorySize, GEMM_SMEM);
        cudaFuncSetAttribute(gemm_mma<1>,
                             cudaFuncAttributeMaxDynamicSharedMemorySize, GEMM_SMEM);
        attr_set = true;
    }

    const int M = Bc * Tc;       // 8192

    // 0) prep: round x; transpose+round weights -> K-major [N, K]
    {
        const int nx = M * Cc;
        round_kernel<<<nx / (256 * 4), 256>>>(x, xr, nx);
        dim3 g1(3 * Cc / 32, Cc / 32);
        transpose_kernel<<<g1, 256>>>(Wqkv, wqkvT, Cc, 3 * Cc);
        dim3 g2(Cc / 32, Cc / 32);
        transpose_kernel<<<g2, 256>>>(Wout, woutT, Cc, Cc);
    }

    // 1) QKV GEMM + bias (tf32 mma.sync) -> g_qkv [s][B][H][T][D], rounded
    {
        dim3 grid((3 * Cc) / 128, M / 128);   // (24, 64)
        gemm_mma<1><<<grid, 256, GEMM_SMEM>>>(xr, wqkvT, bqkv, nullptr, M, 3 * Cc, Cc);
    }

    // 2) causal flash attention (tf32 mma.sync) -> g_att [B,T,C], rounded
    {
        const float* Qp = qkv;
        const float* Kp = qkv + BHTD;
        const float* Vp = qkv + 2 * BHTD;
        dim3 grid(Tc / 64, Bc * Hc);          // (32, 64)
        attn_mma_kernel<<<grid, 128, ATT_SMEM>>>(Qp, Kp, Vp, att);
    }

    // 3) output projection + bias (tf32 mma.sync) -> d_out
    {
        dim3 grid(Cc / 128, M / 128);         // (8, 64)
        gemm_mma<0><<<grid, 256, GEMM_SMEM>>>(att, woutT, bout, out, M, Cc, Cc);
    }
}

// round 13
// speedup vs baseline: 4.6563x; 1.0354x over previous
#include <cuda_runtime.h>
#include <cstdint>

// Problem constants
#define Bc 4
#define Tc 2048
#define Cc 1024
#define Hc 16
#define Dc 64
#define BHTD ((size_t)Bc * Hc * Tc * Dc)   // 8388608

// Scratch (static device globals — no allocation allowed)
// g_qkv: Q,K segments [b][h][T][D]; V segment stored TRANSPOSED [b][h][D][T]
__device__ float g_qkv[3 * Bc * Hc * Tc * Dc];
__device__ float g_att[(size_t)Bc * Tc * Cc];          // [B,T,C] (tf32-rounded)
__device__ float g_xr[(size_t)Bc * Tc * Cc];           // x, tf32-rounded
__device__ float g_wqkvT[3 * Cc * Cc];                 // Wqkv^T [3072,1024], tf32-rounded
__device__ float g_woutT[(size_t)Cc * Cc];             // Wout^T [1024,1024], tf32-rounded

__device__ __forceinline__ float neg_inf() { return __int_as_float(0xff800000); }

__device__ __forceinline__ float tf32r(float x) {
    float y;
    asm("cvt.rna.tf32.f32 %0, %1;" : "=f"(y) : "f"(x));
    return y;
}

__device__ __forceinline__ uint32_t smem_u32(const void* p) {
    uint32_t a;
    asm("{ .reg .u64 t; cvta.to.shared.u64 t, %1; cvt.u32.u64 %0, t; }"
        : "=r"(a) : "l"(p));
    return a;
}

__device__ __forceinline__ void cp_async16(uint32_t smem_dst, const void* gsrc) {
    asm volatile("cp.async.cg.shared.global [%0], [%1], 16;"
                 :: "r"(smem_dst), "l"(gsrc) : "memory");
}
__device__ __forceinline__ void cp_async_commit() {
    asm volatile("cp.async.commit_group;" ::: "memory");
}
__device__ __forceinline__ void cp_async_wait1() {
    asm volatile("cp.async.wait_group 1;" ::: "memory");
}
__device__ __forceinline__ void cp_async_wait0() {
    asm volatile("cp.async.wait_group 0;" ::: "memory");
}

// mma.sync m16n8k8 tf32 (A row-major, B col-major, fp32 accum)
__device__ __forceinline__ void mma_tf32(float* d, const uint32_t* a, const uint32_t* b) {
    asm volatile(
        "mma.sync.aligned.m16n8k8.row.col.f32.tf32.tf32.f32 "
        "{%0,%1,%2,%3}, {%4,%5,%6,%7}, {%8,%9}, {%0,%1,%2,%3};"
        : "+f"(d[0]), "+f"(d[1]), "+f"(d[2]), "+f"(d[3])
        : "r"(a[0]), "r"(a[1]), "r"(a[2]), "r"(a[3]), "r"(b[0]), "r"(b[1]));
}

// ldmatrix x4: four 8-row x 16-byte matrices (== four 8x4 tf32 tiles)
__device__ __forceinline__ void ldsm4(uint32_t* r, uint32_t addr) {
    asm volatile("ldmatrix.sync.aligned.m8n8.x4.shared.b16 {%0,%1,%2,%3}, [%4];"
        : "=r"(r[0]), "=r"(r[1]), "=r"(r[2]), "=r"(r[3]) : "r"(addr));
}

// ---------------------------------------------------------------------------
// Elementwise tf32 rounding
// ---------------------------------------------------------------------------
__global__ __launch_bounds__(256)
void round_kernel(const float* __restrict__ in, float* __restrict__ out, int n)
{
    const int i = (blockIdx.x * 256 + threadIdx.x) * 4;
    if (i < n) {
        float4 v = *(const float4*)(in + i);
        v.x = tf32r(v.x); v.y = tf32r(v.y); v.z = tf32r(v.z); v.w = tf32r(v.w);
        *(float4*)(out + i) = v;
    }
}

// ---------------------------------------------------------------------------
// Transpose + tf32 round: out[c][r] = rna_tf32(in[r][c])  (R rows, C cols)
// ---------------------------------------------------------------------------
__global__ __launch_bounds__(256)
void transpose_kernel(const float* __restrict__ in, float* __restrict__ out,
                      int R, int C)
{
    __shared__ float tile[32][33];
    const int c0 = blockIdx.x * 32;
    const int r0 = blockIdx.y * 32;
    const int x = threadIdx.x & 31;
    const int y = threadIdx.x >> 5;
#pragma unroll
    for (int i = 0; i < 32; i += 8)
        tile[y + i][x] = in[(size_t)(r0 + y + i) * C + c0 + x];
    __syncthreads();
#pragma unroll
    for (int i = 0; i < 32; i += 8)
        out[(size_t)(c0 + y + i) * R + r0 + x] = tf32r(tile[x][y + i]);
}

// ---------------------------------------------------------------------------
// tf32 mma.sync GEMM:  C[M,N] = A[M,K] @ Bt[N,K]^T + bias
// CTA 128x128, 256 threads = 8 warps (2m x 4n), warp tile 64x32, BK=32,
// 3-stage cp.async pipeline, ldmatrix.x4 loads, warp-staggered ks order.
// MODE 0: plain write.  MODE 1: scatter into g_qkv (tf32-rounded;
//         V segment written TRANSPOSED as [b][h][D][T]).
// ---------------------------------------------------------------------------
#define PAD32 36                                 // 32 data + 4 pad floats
#define GSTG32 (128 * PAD32)                     // floats per operand per stage
#define GEMM_SMEM (2 * 3 * GSTG32 * 4)           // 110592 bytes

template <int MODE>
__global__ __launch_bounds__(256, 2)
void gemm_mma(const float* __restrict__ A, const float* __restrict__ Bt,
              const float* __restrict__ bias, float* __restrict__ Cout,
              int M, int N, int K)
{
    extern __shared__ float sm[];
    float* As = sm;                  // [3][GSTG32]
    float* Bs = sm + 3 * GSTG32;     // [3][GSTG32]

    const int tid = threadIdx.x;
    const int wid = tid >> 5;            // 0..7
    const int lid = tid & 31;
    const int g   = lid >> 2;
    const int tg  = lid & 3;
    const int wm  = (wid >> 2) * 64;     // 2 m-groups
    const int wn  = (wid & 3) * 32;      // 4 n-groups

    const int m0 = blockIdx.y * 128;
    const int n0 = blockIdx.x * 128;
    const int KT = K >> 5;               // BK=32 tiles

    // ldmatrix per-lane row/col (in floats) within a ks-block
    const int a_r = ((lid >> 3) & 1) * 8 + (lid & 7);
    const int a_c = (lid >> 4) * 4;
    const int b_r = (lid >> 4) * 8 + (lid & 7);
    const int b_c = ((lid >> 3) & 1) * 4;

    float acc[4][4][4];
#pragma unroll
    for (int i = 0; i < 4; i++)
#pragma unroll
        for (int j = 0; j < 4; j++)
#pragma unroll
            for (int r = 0; r < 4; r++) acc[i][j][r] = 0.0f;

    auto load_stage = [&](int kt, int stg) {
        const float* ga = A  + (size_t)m0 * K + kt * 32;
        const float* gb = Bt + (size_t)n0 * K + kt * 32;
        const uint32_t sa = smem_u32(As + stg * GSTG32);
        const uint32_t sb = smem_u32(Bs + stg * GSTG32);
#pragma unroll
        for (int i = 0; i < 4; i++) {
            const int c = tid + i * 256;          // 0..1023
            const int row = c >> 3;               // 0..127
            const int c16 = c & 7;                // 16B chunk in row
            cp_async16(sa + (row * PAD32 + c16 * 4) * 4, ga + (size_t)row * K + c16 * 4);
            cp_async16(sb + (row * PAD32 + c16 * 4) * 4, gb + (size_t)row * K + c16 * 4);
        }
        cp_async_commit();
    };

    load_stage(0, 0);
    load_stage(1, 1);

    int cur = 0;
    for (int kt = 0; kt < KT; kt++) {
        if (kt + 1 < KT) cp_async_wait1();   // tile kt resident
        else             cp_async_wait0();   // last tile: everything done
        __syncthreads();
        const int nxt = (cur + 2 >= 3) ? cur - 1 : cur + 2;
        if (kt + 2 < KT) load_stage(kt + 2, nxt);

        const uint32_t au = smem_u32(As + cur * GSTG32) + 4u * ((wm + a_r) * PAD32 + a_c);
        const uint32_t bu = smem_u32(Bs + cur * GSTG32) + 4u * ((wn + b_r) * PAD32 + b_c);

#pragma unroll
        for (int p = 0; p < 4; p++) {
            const int ks = (p + wid) & 3;    // warp-staggered phase
            uint32_t af[4][4], bf[4][2];
#pragma unroll
            for (int i = 0; i < 4; i++)
                ldsm4(af[i], au + 4u * (i * 16 * PAD32 + ks * 8));
#pragma unroll
            for (int jp = 0; jp < 2; jp++) {
                uint32_t r[4];
                ldsm4(r, bu + 4u * (jp * 16 * PAD32 + ks * 8));
                bf[2 * jp][0]     = r[0];
                bf[2 * jp][1]     = r[1];
                bf[2 * jp + 1][0] = r[2];
                bf[2 * jp + 1][1] = r[3];
            }
#pragma unroll
            for (int i = 0; i < 4; i++)
#pragma unroll
                for (int j = 0; j < 4; j++)
                    mma_tf32(acc[i][j], af[i], bf[j]);
        }
        cur = (cur + 1 >= 3) ? 0 : cur + 1;
    }

    // epilogue
#pragma unroll
    for (int i = 0; i < 4; i++) {
        const int r0 = m0 + wm + i * 16 + g;
        const int r1 = r0 + 8;
#pragma unroll
        for (int j = 0; j < 4; j++) {
            const int c = n0 + wn + j * 8 + 2 * tg;
            const float2 bv = *(const float2*)(bias + c);
            float2 v0, v1;
            v0.x = acc[i][j][0] + bv.x;  v0.y = acc[i][j][1] + bv.y;
            v1.x = acc[i][j][2] + bv.x;  v1.y = acc[i][j][3] + bv.y;
            if (MODE == 0) {
                *(float2*)(Cout + (size_t)r0 * N + c) = v0;
                *(float2*)(Cout + (size_t)r1 * N + c) = v1;
            } else {
                // qkv feeds tf32 attention mmas -> round at the source
                v0.x = tf32r(v0.x); v0.y = tf32r(v0.y);
                v1.x = tf32r(v1.x); v1.y = tf32r(v1.y);
                const int sidx = c >> 10;
                const int rem  = c & (Cc - 1);
                const int h    = rem >> 6;
                const int dd   = rem & (Dc - 1);
                const int b0i = r0 >> 11, t0i = r0 & (Tc - 1);
                const int b1i = r1 >> 11, t1i = r1 & (Tc - 1);
                const size_t bh0 = (size_t)(sidx * Bc + b0i) * Hc + h;
                const size_t bh1 = (size_t)(sidx * Bc + b1i) * Hc + h;
                if (sidx < 2) {
                    *(float2*)&g_qkv[(bh0 * Tc + t0i) * 64 + dd] = v0;
                    *(float2*)&g_qkv[(bh1 * Tc + t1i) * 64 + dd] = v1;
                } else {
                    // V transposed: [bh][d][t]
                    float* p0 = &g_qkv[bh0 * ((size_t)64 * Tc) + (size_t)dd * Tc + t0i];
                    float* p1 = &g_qkv[bh1 * ((size_t)64 * Tc) + (size_t)dd * Tc + t1i];
                    p0[0]  = v0.x;  p0[Tc] = v0.y;
                    p1[0]  = v1.x;  p1[Tc] = v1.y;
                }
            }
        }
    }
}

// ---------------------------------------------------------------------------
// Tensor-core causal flash attention (tf32 mma.sync), ldmatrix everywhere.
// CTA: 64 queries of one (b,h); 4 warps x 16 rows. Key blocks of 64.
// K smem [64 keys][68]; V smem holds V^T tile [64 d][68] (from [bh][D][T]
// global layout) so PV B-frags use the same ldmatrix pattern as K.
// P round-trips per-warp smem; frags via ldmatrix (rows 272B = 16B-aligned).
// ---------------------------------------------------------------------------
#define KS_ST 68
#define PS_ST 68
#define ATT_SMEM ((64 * KS_ST + 64 * KS_ST + 4 * 16 * PS_ST) * 4)   // 52224 B

__global__ __launch_bounds__(128)
void attn_mma_kernel(const float* __restrict__ Q, const float* __restrict__ K,
                     const float* __restrict__ VT, float* __restrict__ O)
{
    extern __shared__ float sm[];
    float* Ks = sm;                       // [64][68]  (rows = keys)
    float* Vs = sm + 64 * KS_ST;          // [64][68]  (rows = d)
    float* Ps = Vs + 64 * KS_ST;          // [4][16][68]

    const int tid = threadIdx.x;
    const int wid = tid >> 5;
    const int lid = tid & 31;
    const int g   = lid >> 2;
    const int tg  = lid & 3;
    const int bh  = blockIdx.y;
    const int b   = bh >> 4;
    const int h   = bh & 15;
    const int qb  = gridDim.x - 1 - blockIdx.x;   // heavy blocks first
    const int q0  = qb * 64;

    // ldmatrix per-lane row/col (floats)
    const int a_r = ((lid >> 3) & 1) * 8 + (lid & 7);
    const int a_c = (lid >> 4) * 4;
    const int b_r = (lid >> 4) * 8 + (lid & 7);
    const int b_c = ((lid >> 3) & 1) * 4;

    const float SCALE = 0.125f * 1.44269504088896340736f;

    const float* qbase = Q + ((size_t)bh * Tc + q0 + wid * 16) * Dc;
    uint32_t qf[8][4];
#pragma unroll
    for (int k = 0; k < 8; k++) {
        qf[k][0] = __float_as_uint(tf32r(qbase[(size_t)g * Dc       + 8 * k + tg]     * SCALE));
        qf[k][1] = __float_as_uint(tf32r(qbase[(size_t)(g + 8) * Dc + 8 * k + tg]     * SCALE));
        qf[k][2] = __float_as_uint(tf32r(qbase[(size_t)g * Dc       + 8 * k + tg + 4] * SCALE));
        qf[k][3] = __float_as_uint(tf32r(qbase[(size_t)(g + 8) * Dc + 8 * k + tg + 4] * SCALE));
    }

    float o[8][4];
#pragma unroll
    for (int nt = 0; nt < 8; nt++)
#pragma unroll
        for (int r = 0; r < 4; r++) o[nt][r] = 0.0f;
    float m0 = neg_inf(), m1 = neg_inf(), l0 = 0.0f, l1 = 0.0f;

    const float* kg  = K  + (size_t)bh * Tc * Dc;           // [t][d]
    const float* vtg = VT + (size_t)bh * Dc * Tc;           // [d][t]
    const uint32_t ksu = smem_u32(Ks);
    const uint32_t vsu = smem_u32(Vs);
    float* Pw = Ps + wid * 16 * PS_ST;

    const uint32_t ku = ksu + 4u * (b_r * KS_ST + b_c);
    const uint32_t vu = vsu + 4u * (b_r * KS_ST + b_c);
    const uint32_t pu = smem_u32(Pw) + 4u * (a_r * PS_ST + a_c);

    auto load_k = [&](int t0) {
#pragma unroll
        for (int i = 0; i < 8; i++) {
            const int c = tid + i * 128;
            const int row = c >> 4;              // key index
            const int c16 = c & 15;
            cp_async16(ksu + (row * KS_ST + c16 * 4) * 4,
                       kg + (size_t)(t0 + row) * Dc + c16 * 4);
        }
        cp_async_commit();
    };
    auto load_v = [&](int t0) {
#pragma unroll
        for (int i = 0; i < 8; i++) {
            const int c = tid + i * 128;
            const int row = c >> 4;              // d index
            const int c16 = c & 15;
            cp_async16(vsu + (row * KS_ST + c16 * 4) * 4,
                       vtg + (size_t)row * Tc + t0 + c16 * 4);
        }
        cp_async_commit();
    };

    const int NT = qb + 1;
    load_k(0);
    load_v(0);

    for (int it = 0; it < NT; it++) {
        const int t0 = it * 64;

        cp_async_wait1();            // K_it resident (V_it is the newer group)
        __syncthreads();

        // S = Q K^T   (16 x 64 per warp), K-frags via ldmatrix
        float s[8][4];
#pragma unroll
        for (int nt = 0; nt < 8; nt++)
            s[nt][0] = s[nt][1] = s[nt][2] = s[nt][3] = 0.0f;
#pragma unroll
        for (int ks = 0; ks < 8; ks++) {
            uint32_t bf[8][2];
#pragma unroll
            for (int jp = 0; jp < 4; jp++) {
                uint32_t r[4];
                ldsm4(r, ku + 4u * (jp * 16 * KS_ST + ks * 8));
                bf[2 * jp][0]     = r[0];
                bf[2 * jp][1]     = r[1];
                bf[2 * jp + 1][0] = r[2];
                bf[2 * jp + 1][1] = r[3];
            }
#pragma unroll
            for (int nt = 0; nt < 8; nt++)
                mma_tf32(s[nt], qf[ks], bf[nt]);
        }

        __syncthreads();             // all warps done reading Ks
        if (it + 1 < NT) load_k(t0 + 64);   // overlaps softmax + PV below

        if (t0 == q0) {              // causal mask on diagonal block
            const int r0 = wid * 16 + g;
            const int r1 = r0 + 8;
#pragma unroll
            for (int nt = 0; nt < 8; nt++) {
                const int c0i = nt * 8 + 2 * tg;
                if (c0i     > r0) s[nt][0] = neg_inf();
                if (c0i + 1 > r0) s[nt][1] = neg_inf();
                if (c0i     > r1) s[nt][2] = neg_inf();
                if (c0i + 1 > r1) s[nt][3] = neg_inf();
            }
        }

        float mt0 = m0, mt1 = m1;
#pragma unroll
        for (int nt = 0; nt < 8; nt++) {
            mt0 = fmaxf(mt0, fmaxf(s[nt][0], s[nt][1]));
            mt1 = fmaxf(mt1, fmaxf(s[nt][2], s[nt][3]));
        }
        mt0 = fmaxf(mt0, __shfl_xor_sync(0xffffffffu, mt0, 1));
        mt0 = fmaxf(mt0, __shfl_xor_sync(0xffffffffu, mt0, 2));
        mt1 = fmaxf(mt1, __shfl_xor_sync(0xffffffffu, mt1, 1));
        mt1 = fmaxf(mt1, __shfl_xor_sync(0xffffffffu, mt1, 2));

        const float a0 = exp2f(m0 - mt0);
        const float a1 = exp2f(m1 - mt1);
        m0 = mt0; m1 = mt1;
        l0 *= a0;  l1 *= a1;
#pragma unroll
        for (int nt = 0; nt < 8; nt++) {
            o[nt][0] *= a0; o[nt][1] *= a0;
            o[nt][2] *= a1; o[nt][3] *= a1;
        }

#pragma unroll
        for (int nt = 0; nt < 8; nt++) {
            float p00 = exp2f(s[nt][0] - mt0);
            float p01 = exp2f(s[nt][1] - mt0);
            float p10 = exp2f(s[nt][2] - mt1);
            float p11 = exp2f(s[nt][3] - mt1);
            p00 = tf32r(p00); p01 = tf32r(p01);
            p10 = tf32r(p10); p11 = tf32r(p11);
            l0 += p00 + p01;
            l1 += p10 + p11;
            *(float2*)&Pw[g * PS_ST + nt * 8 + 2 * tg]       = make_float2(p00, p01);
            *(float2*)&Pw[(g + 8) * PS_ST + nt * 8 + 2 * tg] = make_float2(p10, p11);
        }
        __syncwarp();

        if (it + 1 < NT) cp_async_wait1();   // V_it resident (K_{it+1} in flight)
        else             cp_async_wait0();   // final V: guarantee completion
        __syncthreads();

        // O += P V : P-frags and V-frags via ldmatrix
#pragma unroll
        for (int ks = 0; ks < 8; ks++) {
            uint32_t af[4];
            ldsm4(af, pu + 4u * (ks * 8));
            uint32_t bf[8][2];
#pragma unroll
            for (int jp = 0; jp < 4; jp++) {
                uint32_t r[4];
                ldsm4(r, vu + 4u * (jp * 16 * KS_ST + ks * 8));
                bf[2 * jp][0]     = r[0];
                bf[2 * jp][1]     = r[1];
                bf[2 * jp + 1][0] = r[2];
                bf[2 * jp + 1][1] = r[3];
            }
#pragma unroll
            for (int nt = 0; nt < 8; nt++)
                mma_tf32(o[nt], af, bf[nt]);
        }

        __syncthreads();             // all warps done reading Vs
        if (it + 1 < NT) load_v(t0 + 64);   // overlaps next S
    }

    l0 += __shfl_xor_sync(0xffffffffu, l0, 1);
    l0 += __shfl_xor_sync(0xffffffffu, l0, 2);
    l1 += __shfl_xor_sync(0xffffffffu, l1, 1);
    l1 += __shfl_xor_sync(0xffffffffu, l1, 2);
    const float inv0 = 1.0f / l0;
    const float inv1 = 1.0f / l1;

    const int row0 = q0 + wid * 16 + g;
    const int row1 = row0 + 8;
    float* ob0 = O + ((size_t)b * Tc + row0) * Cc + h * Dc;
    float* ob1 = O + ((size_t)b * Tc + row1) * Cc + h * Dc;
#pragma unroll
    for (int nt = 0; nt < 8; nt++) {
        const int c = nt * 8 + 2 * tg;
        *(float2*)(ob0 + c) = make_float2(tf32r(o[nt][0] * inv0), tf32r(o[nt][1] * inv0));
        *(float2*)(ob1 + c) = make_float2(tf32r(o[nt][2] * inv1), tf32r(o[nt][3] * inv1));
    }
}

// ---------------------------------------------------------------------------
// Host launcher
// ---------------------------------------------------------------------------
extern "C" void kernel_launch(void* const* d_in, const int* in_sizes, int n_in,
                              void* d_out, int out_size)
{
    const float* x    = (const float*)d_in[0];
    // d_in[1] = mask (static causal — unused)
    const float* Wqkv = (const float*)d_in[2];
    const float* bqkv = (const float*)d_in[3];
    const float* Wout = (const float*)d_in[4];
    const float* bout = (const float*)d_in[5];
    float* out = (float*)d_out;

    float* qkv = nullptr;
    float* att = nullptr;
    float* xr = nullptr;
    float* wqkvT = nullptr;
    float* woutT = nullptr;
    cudaGetSymbolAddress((void**)&qkv, g_qkv);
    cudaGetSymbolAddress((void**)&att, g_att);
    cudaGetSymbolAddress((void**)&xr, g_xr);
    cudaGetSymbolAddress((void**)&wqkvT, g_wqkvT);
    cudaGetSymbolAddress((void**)&woutT, g_woutT);

    static bool attr_set = false;
    if (!attr_set) {
        cudaFuncSetAttribute(attn_mma_kernel,
                             cudaFuncAttributeMaxDynamicSharedMemorySize, ATT_SMEM);
        cudaFuncSetAttribute(gemm_mma<0>,
                             cudaFuncAttributeMaxDynamicSharedMemorySize, GEMM_SMEM);
        cudaFuncSetAttribute(gemm_mma<1>,
                             cudaFuncAttributeMaxDynamicSharedMemorySize, GEMM_SMEM);
        attr_set = true;
    }

    const int M = Bc * Tc;       // 8192

    // 0) prep: round x; transpose+round weights -> K-major [N, K]
    {
        const int nx = M * Cc;
        round_kernel<<<nx / (256 * 4), 256>>>(x, xr, nx);
        dim3 g1(3 * Cc / 32, Cc / 32);
        transpose_kernel<<<g1, 256>>>(Wqkv, wqkvT, Cc, 3 * Cc);
        dim3 g2(Cc / 32, Cc / 32);
        transpose_kernel<<<g2, 256>>>(Wout, woutT, Cc, Cc);
    }

    // 1) QKV GEMM + bias (tf32 mma.sync) -> g_qkv (V transposed), rounded
    {
        dim3 grid((3 * Cc) / 128, M / 128);   // (24, 64)
        gemm_mma<1><<<grid, 256, GEMM_SMEM>>>(xr, wqkvT, bqkv, nullptr, M, 3 * Cc, Cc);
    }

    // 2) causal flash attention (tf32 mma.sync) -> g_att [B,T,C], rounded
    {
        const float* Qp  = qkv;
        const float* Kp  = qkv + BHTD;
        const float* VTp = qkv + 2 * BHTD;    // [b][h][D][T]
        dim3 grid(Tc / 64, Bc * Hc);          // (32, 64)
        attn_mma_kernel<<<grid, 128, ATT_SMEM>>>(Qp, Kp, VTp, att);
    }

    // 3) output projection + bias (tf32 mma.sync) -> d_out
    {
        dim3 grid(Cc / 128, M / 128);         // (8, 64)
        gemm_mma<0><<<grid, 256, GEMM_SMEM>>>(att, woutT, bout, out, M, Cc, Cc);
    }
}